// round 11
// baseline (speedup 1.0000x reference)
#include <cuda_runtime.h>
#include <cuda_bf16.h>
#include <math.h>
#include <stdint.h>

#define BN   4
#define CN   256
#define HWN  4096
#define DN   128
#define TM   128            // queries per CTA (attention)
#define TN   64             // keys per tile
#define LOG2E 1.4426950408889634f

// attention smem stage layout (bytes)
#define K_ROW   272
#define V_ROW   144
#define KH_OFF  0
#define KL_OFF  (64 * K_ROW)
#define VH_OFF  (2 * 64 * K_ROW)
#define VL_OFF  (2 * 64 * K_ROW + 128 * V_ROW)
#define STG_SZ  (2 * 64 * K_ROW + 2 * 128 * V_ROW)   // 71680
#define ATTN_SMEM (2 * STG_SZ)                        // 143360

// proj smem (bytes): x planes [64][144B], w planes [128][144B]
#define PXH 0
#define PXL 9216
#define PWH 18432
#define PWL 36864
#define PRJ_SMEM 55296

// wgemm smem: y planes [64][272B]
#define WYH 0
#define WYL 17408
#define WG_SMEM 34816

// -------------------- scratch --------------------
__device__ __align__(128) __nv_bfloat16 gXh[BN * HWN * CN];  // x^T hi [b][n][c]
__device__ __align__(128) __nv_bfloat16 gXl[BN * HWN * CN];
__device__ __align__(128) __nv_bfloat16 gWh[3 * DN * CN];    // proj weights hi [p][i][c]
__device__ __align__(128) __nv_bfloat16 gWl[3 * DN * CN];
__device__ __align__(128) __nv_bfloat16 gWWh[CN * DN];       // W hi [c][i]
__device__ __align__(128) __nv_bfloat16 gWWl[CN * DN];
__device__ __align__(128) __nv_bfloat16 gQh[BN * HWN * DN];  // theta hi [b][n][k]
__device__ __align__(128) __nv_bfloat16 gQl[BN * HWN * DN];
__device__ __align__(128) __nv_bfloat16 gKh[BN * HWN * DN];  // phi(scaled) hi [b][m][k]
__device__ __align__(128) __nv_bfloat16 gKl[BN * HWN * DN];
__device__ __align__(128) __nv_bfloat16 gVh[BN * DN * HWN];  // g hi [b][d][m]
__device__ __align__(128) __nv_bfloat16 gVl[BN * DN * HWN];
__device__ __align__(128) __nv_bfloat16 gYh[BN * HWN * DN];  // attn out hi [b][n][i]
__device__ __align__(128) __nv_bfloat16 gYl[BN * HWN * DN];
__device__ __align__(128) float d_WY[BN * CN * HWN];         // [b][c][n]
__device__ float gPS[CN * 256];
__device__ float gPQ[CN * 256];
__device__ float d_MEAN[CN];
__device__ float d_RSTD[CN];

// ======================= helpers =======================
__device__ __forceinline__ uint32_t smem_u32(const void* p) {
    uint32_t a;
    asm("{ .reg .u64 t; cvta.to.shared.u64 t, %1; cvt.u32.u64 %0, t; }" : "=r"(a) : "l"(p));
    return a;
}
__device__ __forceinline__ void cp16(uint32_t dst, const void* src) {
    asm volatile("cp.async.cg.shared.global [%0], [%1], 16;" :: "r"(dst), "l"(src));
}
#define CP_COMMIT() asm volatile("cp.async.commit_group;" ::: "memory")
#define CP_WAIT0()  asm volatile("cp.async.wait_group 0;" ::: "memory")
#define CP_WAIT1()  asm volatile("cp.async.wait_group 1;" ::: "memory")

__device__ __forceinline__ void mma_bf16(float& c0, float& c1, float& c2, float& c3,
                                         uint32_t a0, uint32_t a1, uint32_t a2, uint32_t a3,
                                         uint32_t b0, uint32_t b1) {
    asm volatile("mma.sync.aligned.m16n8k16.row.col.f32.bf16.bf16.f32 "
                 "{%0,%1,%2,%3}, {%4,%5,%6,%7}, {%8,%9}, {%0,%1,%2,%3};"
                 : "+f"(c0), "+f"(c1), "+f"(c2), "+f"(c3)
                 : "r"(a0), "r"(a1), "r"(a2), "r"(a3), "r"(b0), "r"(b1));
}
__device__ __forceinline__ uint32_t lds32(uint32_t addr) {
    uint32_t v;
    asm volatile("ld.shared.b32 %0, [%1];" : "=r"(v) : "r"(addr));
    return v;
}
__device__ __forceinline__ void ldsm4(uint32_t& r0, uint32_t& r1, uint32_t& r2, uint32_t& r3,
                                      uint32_t addr) {
    asm volatile("ldmatrix.sync.aligned.m8n8.x4.shared.b16 {%0,%1,%2,%3}, [%4];"
                 : "=r"(r0), "=r"(r1), "=r"(r2), "=r"(r3) : "r"(addr));
}
__device__ __forceinline__ float ex2(float x) {
    float y;
    asm("ex2.approx.ftz.f32 %0, %1;" : "=f"(y) : "f"(x));
    return y;
}
__device__ __forceinline__ void split2(float v0, float v1, uint32_t& hi, uint32_t& lo) {
    __nv_bfloat16 h0 = __float2bfloat16(v0);
    __nv_bfloat16 h1 = __float2bfloat16(v1);
    float r0 = v0 - __bfloat162float(h0);
    float r1 = v1 - __bfloat162float(h1);
    __nv_bfloat162 hh; hh.x = h0; hh.y = h1;
    __nv_bfloat162 ll; ll.x = __float2bfloat16(r0); ll.y = __float2bfloat16(r1);
    hi = *(uint32_t*)&hh;
    lo = *(uint32_t*)&ll;
}
__device__ __forceinline__ void split1(float v, unsigned short& h, unsigned short& l) {
    __nv_bfloat16 hb = __float2bfloat16(v);
    float r = v - __bfloat162float(hb);
    __nv_bfloat16 lb = __float2bfloat16(r);
    h = *(unsigned short*)&hb;
    l = *(unsigned short*)&lb;
}

// ============================================================================
// K0: pre-split all weights to bf16 hi/lo.
// ============================================================================
__global__ void wsplit_kernel(const float* __restrict__ tw, const float* __restrict__ pw,
                              const float* __restrict__ gw, const float* __restrict__ Ww)
{
    int idx = blockIdx.x * 256 + threadIdx.x;
    if (idx < 49152) {
        int p = idx / 16384, r = idx - p * 16384;
        const float* s = (p == 0) ? tw : (p == 1) ? pw : gw;
        float2 v = *(const float2*)(s + 2 * r);
        uint32_t hi, lo;
        split2(v.x, v.y, hi, lo);
        *(uint32_t*)(gWh + p * 32768 + 2 * r) = hi;
        *(uint32_t*)(gWl + p * 32768 + 2 * r) = lo;
    } else {
        int r = idx - 49152;
        float2 v = *(const float2*)(Ww + 2 * r);
        uint32_t hi, lo;
        split2(v.x, v.y, hi, lo);
        *(uint32_t*)(gWWh + 2 * r) = hi;
        *(uint32_t*)(gWWl + 2 * r) = lo;
    }
}

// ============================================================================
// K0b: transpose+split x -> xT hi/lo [b][n][c].
// ============================================================================
__global__ void xsplit_kernel(const float* __restrict__ x)
{
    __shared__ float xs[64][68];
    const int n0 = blockIdx.x * 64;
    const int c0 = blockIdx.y * 64;
    const int b  = blockIdx.z;
    const int tid = threadIdx.x;
#pragma unroll
    for (int r = 0; r < 4; r++) {
        int fid = tid + (r << 8);
        int cc = fid >> 4, n4 = fid & 15;
        float4 v = *(const float4*)(x + ((size_t)b * CN + c0 + cc) * HWN + n0 + 4 * n4);
        *(float4*)&xs[cc][4 * n4] = v;
    }
    __syncthreads();
#pragma unroll
    for (int r = 0; r < 8; r++) {
        int fid = tid + (r << 8);
        int n = fid >> 5, cp = fid & 31;
        float a  = xs[2 * cp][n];
        float bb = xs[2 * cp + 1][n];
        uint32_t hi, lo;
        split2(a, bb, hi, lo);
        size_t gi = ((size_t)b * HWN + n0 + n) * CN + c0 + 2 * cp;
        *(uint32_t*)(gXh + gi) = hi;
        *(uint32_t*)(gXl + gi) = lo;
    }
}

// ============================================================================
// K1: projections via mma.sync (pre-split operands).
// ============================================================================
__global__ void __launch_bounds__(256) proj_mma_kernel(
    const float* __restrict__ tb, const float* __restrict__ pb, const float* __restrict__ gb)
{
    extern __shared__ char psm[];
    const uint32_t smb = smem_u32(psm);
    unsigned short* sth = (unsigned short*)(psm);            // stage hi [64][130]
    unsigned short* stl = (unsigned short*)(psm + 16640);    // stage lo [64][130]

    const int p  = blockIdx.x;
    const int n0 = blockIdx.y * 64;
    const int b  = blockIdx.z;
    const float* bias = (p == 0) ? tb : (p == 1) ? pb : gb;

    const int tid  = threadIdx.x;
    const int wrp  = tid >> 5;
    const int lane = tid & 31;
    const int qrow = lane >> 2;
    const int qcol = lane & 3;
    const int i0   = 16 * wrp + qrow;

    float acc[8][4];
#pragma unroll
    for (int i = 0; i < 8; i++)
#pragma unroll
        for (int j = 0; j < 4; j++) acc[i][j] = 0.f;

    for (int c0 = 0; c0 < CN; c0 += 64) {
        __syncthreads();
#pragma unroll
        for (int r = 0; r < 4; r++) {
            int fid = tid + (r << 8);
            int pl = fid >> 9, rem = fid & 511;
            int row = rem >> 3, ch = rem & 7;
            const __nv_bfloat16* src = (pl ? gXl : gXh) +
                ((size_t)b * HWN + n0 + row) * CN + c0 + ch * 8;
            cp16(smb + (pl ? PXL : PXH) + row * 144 + ch * 16, src);
        }
#pragma unroll
        for (int r = 0; r < 8; r++) {
            int fid = tid + (r << 8);
            int pl = fid >> 10, rem = fid & 1023;
            int row = rem >> 3, ch = rem & 7;
            const __nv_bfloat16* src = (pl ? gWl : gWh) +
                (size_t)p * 32768 + row * CN + c0 + ch * 8;
            cp16(smb + (pl ? PWL : PWH) + row * 144 + ch * 16, src);
        }
        CP_COMMIT();
        CP_WAIT0();
        __syncthreads();

        uint32_t ah[4][4], al[4][4];
#pragma unroll
        for (int ks = 0; ks < 4; ks++) {
            uint32_t ko = 32 * ks + 4 * qcol;
            ah[ks][0] = lds32(smb + PWH + i0 * 144 + ko);
            ah[ks][1] = lds32(smb + PWH + (i0 + 8) * 144 + ko);
            ah[ks][2] = lds32(smb + PWH + i0 * 144 + ko + 16);
            ah[ks][3] = lds32(smb + PWH + (i0 + 8) * 144 + ko + 16);
            al[ks][0] = lds32(smb + PWL + i0 * 144 + ko);
            al[ks][1] = lds32(smb + PWL + (i0 + 8) * 144 + ko);
            al[ks][2] = lds32(smb + PWL + i0 * 144 + ko + 16);
            al[ks][3] = lds32(smb + PWL + (i0 + 8) * 144 + ko + 16);
        }
#pragma unroll
        for (int ks = 0; ks < 4; ks++) {
#pragma unroll
            for (int nt = 0; nt < 8; nt++) {
                uint32_t ro = (8 * nt + qrow) * 144 + 32 * ks + 4 * qcol;
                uint32_t bh0 = lds32(smb + PXH + ro);
                uint32_t bh1 = lds32(smb + PXH + ro + 16);
                uint32_t bl0 = lds32(smb + PXL + ro);
                uint32_t bl1 = lds32(smb + PXL + ro + 16);
                mma_bf16(acc[nt][0], acc[nt][1], acc[nt][2], acc[nt][3],
                         ah[ks][0], ah[ks][1], ah[ks][2], ah[ks][3], bh0, bh1);
                mma_bf16(acc[nt][0], acc[nt][1], acc[nt][2], acc[nt][3],
                         ah[ks][0], ah[ks][1], ah[ks][2], ah[ks][3], bl0, bl1);
                mma_bf16(acc[nt][0], acc[nt][1], acc[nt][2], acc[nt][3],
                         al[ks][0], al[ks][1], al[ks][2], al[ks][3], bh0, bh1);
            }
        }
    }

    const float bb0 = bias[i0];
    const float bb1 = bias[i0 + 8];
    const float sc  = (p == 1) ? LOG2E : 1.f;

    if (p < 2) {
        __syncthreads();
#pragma unroll
        for (int nt = 0; nt < 8; nt++) {
            int n = 8 * nt + 2 * qcol;
            float v0 = (acc[nt][0] + bb0) * sc, v1 = (acc[nt][1] + bb0) * sc;
            float v2 = (acc[nt][2] + bb1) * sc, v3 = (acc[nt][3] + bb1) * sc;
            unsigned short h, l;
            split1(v0, h, l); sth[n * 130 + i0] = h;           stl[n * 130 + i0] = l;
            split1(v1, h, l); sth[(n + 1) * 130 + i0] = h;     stl[(n + 1) * 130 + i0] = l;
            split1(v2, h, l); sth[n * 130 + i0 + 8] = h;       stl[n * 130 + i0 + 8] = l;
            split1(v3, h, l); sth[(n + 1) * 130 + i0 + 8] = h; stl[(n + 1) * 130 + i0 + 8] = l;
        }
        __syncthreads();
        __nv_bfloat16* oh = (p == 0) ? gQh : gKh;
        __nv_bfloat16* ol = (p == 0) ? gQl : gKl;
#pragma unroll
        for (int r = 0; r < 16; r++) {
            int t = tid + (r << 8);
            int row = t >> 6, w32 = t & 63;
            uint32_t hv = *(uint32_t*)&sth[row * 130 + 2 * w32];
            uint32_t lv = *(uint32_t*)&stl[row * 130 + 2 * w32];
            size_t gb_ = ((size_t)b * HWN + n0 + row) * DN + 2 * w32;
            *(uint32_t*)(oh + gb_) = hv;
            *(uint32_t*)(ol + gb_) = lv;
        }
    } else {
#pragma unroll
        for (int nt = 0; nt < 8; nt++) {
            int n = n0 + 8 * nt + 2 * qcol;
            float v0 = acc[nt][0] + bb0, v1 = acc[nt][1] + bb0;
            float v2 = acc[nt][2] + bb1, v3 = acc[nt][3] + bb1;
            uint32_t h01, l01, h23, l23;
            split2(v0, v1, h01, l01);
            split2(v2, v3, h23, l23);
            size_t ba = ((size_t)b * DN + i0) * HWN + n;
            size_t bc = ((size_t)b * DN + i0 + 8) * HWN + n;
            *(uint32_t*)(gVh + ba) = h01;
            *(uint32_t*)(gVl + ba) = l01;
            *(uint32_t*)(gVh + bc) = h23;
            *(uint32_t*)(gVl + bc) = l23;
        }
    }
}

// ============================================================================
// K2: mma.sync bf16 split-2 flash attention (R9 structure + ldmatrix.x4).
// ============================================================================
__device__ __forceinline__ void load_kv_tile(uint32_t stg, int b, int m0, int tid) {
#pragma unroll
    for (int r = 0; r < 4; r++) {
        int ch = tid + (r << 8);
        int rw = ch >> 4;
        int kc = ch & 15;
        uint32_t dst = stg + rw * K_ROW + (kc << 4);
        size_t gi = (((size_t)b * HWN + m0 + rw) << 7) + (kc << 3);
        cp16(dst + KH_OFF, gKh + gi);
        cp16(dst + KL_OFF, gKl + gi);
    }
#pragma unroll
    for (int r = 0; r < 4; r++) {
        int ch = tid + (r << 8);
        int rw = ch >> 3;
        int mc = ch & 7;
        uint32_t dst = stg + rw * V_ROW + (mc << 4);
        size_t gi = (((size_t)b * DN + rw) << 12) + m0 + (mc << 3);
        cp16(dst + VH_OFF, gVh + gi);
        cp16(dst + VL_OFF, gVl + gi);
    }
}

__global__ void __launch_bounds__(256, 1) attn_mma_kernel()
{
    extern __shared__ char smem[];
    const uint32_t smb = smem_u32(smem);

    const int tid  = threadIdx.x;
    const int lane = tid & 31;
    const int wrp  = tid >> 5;
    const int qrow = lane >> 2;
    const int qcol = lane & 3;
    const int n0   = blockIdx.x * TM;
    const int b    = blockIdx.y;
    const int row0 = 16 * wrp + qrow;

    // ldmatrix lane-address bases: matrix id = lane>>3 -> {hi k0, hi k8, lo k0, lo k8}
    const int lr = lane & 7;
    const int lm = lane >> 3;
    const uint32_t koff = (uint32_t)((lm >= 2) ? KL_OFF : KH_OFF) + lr * K_ROW + ((lm & 1) ? 16 : 0);
    const uint32_t voff = (uint32_t)((lm >= 2) ? VL_OFF : VH_OFF) + lr * V_ROW + ((lm & 1) ? 16 : 0);

    uint32_t qh[8][4], ql[8][4];
    {
        const size_t rbase = ((size_t)b * HWN + n0 + row0) * DN;
#pragma unroll
        for (int ks = 0; ks < 8; ks++) {
            int k0 = 16 * ks + 2 * qcol;
            qh[ks][0] = *(const uint32_t*)(gQh + rbase + k0);
            qh[ks][1] = *(const uint32_t*)(gQh + rbase + 8 * DN + k0);
            qh[ks][2] = *(const uint32_t*)(gQh + rbase + k0 + 8);
            qh[ks][3] = *(const uint32_t*)(gQh + rbase + 8 * DN + k0 + 8);
            ql[ks][0] = *(const uint32_t*)(gQl + rbase + k0);
            ql[ks][1] = *(const uint32_t*)(gQl + rbase + 8 * DN + k0);
            ql[ks][2] = *(const uint32_t*)(gQl + rbase + k0 + 8);
            ql[ks][3] = *(const uint32_t*)(gQl + rbase + 8 * DN + k0 + 8);
        }
    }

    float o[16][4];
#pragma unroll
    for (int i = 0; i < 16; i++)
#pragma unroll
        for (int j = 0; j < 4; j++) o[i][j] = 0.f;

    float rs0 = 0.f, rs1 = 0.f;

    load_kv_tile(smb, b, 0, tid);
    CP_COMMIT();

    for (int t = 0; t < 64; t++) {
        const uint32_t stg = smb + (uint32_t)(t & 1) * STG_SZ;
        __syncthreads();
        if (t + 1 < 64) {
            load_kv_tile(smb + (uint32_t)((t + 1) & 1) * STG_SZ, b, (t + 1) * TN, tid);
            CP_COMMIT();
            CP_WAIT1();
        } else {
            CP_WAIT0();
        }
        __syncthreads();

        const uint32_t kb = stg + koff;
        const uint32_t vb = stg + voff;

        // ---- S accumulate: ks-outer / nt-inner (8 independent chains), ldmatrix ----
        float cA[8][4];
#pragma unroll
        for (int nt = 0; nt < 8; nt++)
#pragma unroll
            for (int j = 0; j < 4; j++) cA[nt][j] = 0.f;

#pragma unroll
        for (int ks = 0; ks < 8; ks++) {
#pragma unroll
            for (int nt = 0; nt < 8; nt++) {
                uint32_t bh0, bh1, bl0, bl1;
                ldsm4(bh0, bh1, bl0, bl1, kb + (uint32_t)nt * (8 * K_ROW) + 32 * ks);
                mma_bf16(cA[nt][0], cA[nt][1], cA[nt][2], cA[nt][3],
                         qh[ks][0], qh[ks][1], qh[ks][2], qh[ks][3], bh0, bh1);
                mma_bf16(cA[nt][0], cA[nt][1], cA[nt][2], cA[nt][3],
                         qh[ks][0], qh[ks][1], qh[ks][2], qh[ks][3], bl0, bl1);
                mma_bf16(cA[nt][0], cA[nt][1], cA[nt][2], cA[nt][3],
                         ql[ks][0], ql[ks][1], ql[ks][2], ql[ks][3], bh0, bh1);
            }
        }

        // ---- exp + split ----
        uint32_t ph[8][2], pl[8][2];
#pragma unroll
        for (int nt = 0; nt < 8; nt++) {
            float e0 = ex2(cA[nt][0]), e1 = ex2(cA[nt][1]);
            float e2 = ex2(cA[nt][2]), e3 = ex2(cA[nt][3]);
            rs0 += e0 + e1;
            rs1 += e2 + e3;
            split2(e0, e1, ph[nt][0], pl[nt][0]);
            split2(e2, e3, ph[nt][1], pl[nt][1]);
        }

        // ---- O += P V (16 independent chains), ldmatrix ----
#pragma unroll
        for (int ks = 0; ks < 4; ks++) {
            uint32_t ah0 = ph[2 * ks][0], ah1 = ph[2 * ks][1];
            uint32_t ah2 = ph[2 * ks + 1][0], ah3 = ph[2 * ks + 1][1];
            uint32_t al0 = pl[2 * ks][0], al1 = pl[2 * ks][1];
            uint32_t al2 = pl[2 * ks + 1][0], al3 = pl[2 * ks + 1][1];
            const uint32_t va = vb + 32 * ks;
#pragma unroll
            for (int nt = 0; nt < 16; nt++) {
                uint32_t vh0, vh1, vl0, vl1;
                ldsm4(vh0, vh1, vl0, vl1, va + (uint32_t)nt * (8 * V_ROW));
                mma_bf16(o[nt][0], o[nt][1], o[nt][2], o[nt][3], ah0, ah1, ah2, ah3, vh0, vh1);
                mma_bf16(o[nt][0], o[nt][1], o[nt][2], o[nt][3], ah0, ah1, ah2, ah3, vl0, vl1);
                mma_bf16(o[nt][0], o[nt][1], o[nt][2], o[nt][3], al0, al1, al2, al3, vh0, vh1);
            }
        }
    }

    rs0 += __shfl_xor_sync(0xffffffffu, rs0, 1);
    rs0 += __shfl_xor_sync(0xffffffffu, rs0, 2);
    rs1 += __shfl_xor_sync(0xffffffffu, rs1, 1);
    rs1 += __shfl_xor_sync(0xffffffffu, rs1, 2);
    float inv0 = 1.f / rs0;
    float inv1 = 1.f / rs1;

    const size_t y0 = ((size_t)b * HWN + n0 + row0) * DN + 2 * qcol;
    const size_t y1 = y0 + 8 * DN;
#pragma unroll
    for (int nt = 0; nt < 16; nt++) {
        uint32_t h0, l0, h1, l1;
        split2(o[nt][0] * inv0, o[nt][1] * inv0, h0, l0);
        split2(o[nt][2] * inv1, o[nt][3] * inv1, h1, l1);
        *(uint32_t*)(gYh + y0 + 8 * nt) = h0;
        *(uint32_t*)(gYl + y0 + 8 * nt) = l0;
        *(uint32_t*)(gYh + y1 + 8 * nt) = h1;
        *(uint32_t*)(gYl + y1 + 8 * nt) = l1;
    }
}

// ============================================================================
// K3: wy = W*y + b via mma.sync, operands pre-split; fused BN partials.
// ============================================================================
__global__ void __launch_bounds__(256) wgemm_mma_kernel(const float* __restrict__ Wb)
{
    extern __shared__ char wsm[];
    const uint32_t smb = smem_u32(wsm);

    const int c0 = blockIdx.x * 128;
    const int n0 = blockIdx.y * 64;
    const int b  = blockIdx.z;
    const int part = blockIdx.y * 4 + blockIdx.z;

    const int tid  = threadIdx.x;
    const int lane = tid & 31;
    const int wrp  = tid >> 5;
    const int qrow = lane >> 2;
    const int qcol = lane & 3;
    const int c    = c0 + 16 * wrp + qrow;

#pragma unroll
    for (int r = 0; r < 8; r++) {
        int fid = tid + (r << 8);
        int pl = fid >> 10, rem = fid & 1023;
        int row = rem >> 4, ch = rem & 15;
        const __nv_bfloat16* src = (pl ? gYl : gYh) +
            ((size_t)b * HWN + n0 + row) * DN + ch * 8;
        cp16(smb + (pl ? WYL : WYH) + row * 272 + ch * 16, src);
    }
    CP_COMMIT();

    uint32_t ah[8][4], al[8][4];
#pragma unroll
    for (int ks = 0; ks < 8; ks++) {
        int k = 16 * ks + 2 * qcol;
        ah[ks][0] = *(const uint32_t*)(gWWh + (size_t)c * DN + k);
        ah[ks][1] = *(const uint32_t*)(gWWh + (size_t)(c + 8) * DN + k);
        ah[ks][2] = *(const uint32_t*)(gWWh + (size_t)c * DN + k + 8);
        ah[ks][3] = *(const uint32_t*)(gWWh + (size_t)(c + 8) * DN + k + 8);
        al[ks][0] = *(const uint32_t*)(gWWl + (size_t)c * DN + k);
        al[ks][1] = *(const uint32_t*)(gWWl + (size_t)(c + 8) * DN + k);
        al[ks][2] = *(const uint32_t*)(gWWl + (size_t)c * DN + k + 8);
        al[ks][3] = *(const uint32_t*)(gWWl + (size_t)(c + 8) * DN + k + 8);
    }
    CP_WAIT0();
    __syncthreads();

    float acc[8][4];
#pragma unroll
    for (int i = 0; i < 8; i++)
#pragma unroll
        for (int j = 0; j < 4; j++) acc[i][j] = 0.f;

#pragma unroll
    for (int ks = 0; ks < 8; ks++) {
#pragma unroll
        for (int nt = 0; nt < 8; nt++) {
            uint32_t ro = (8 * nt + qrow) * 272 + 32 * ks + 4 * qcol;
            uint32_t bh0 = lds32(smb + WYH + ro);
            uint32_t bh1 = lds32(smb + WYH + ro + 16);
            uint32_t bl0 = lds32(smb + WYL + ro);
            uint32_t bl1 = lds32(smb + WYL + ro + 16);
            mma_bf16(acc[nt][0], acc[nt][1], acc[nt][2], acc[nt][3],
                     ah[ks][0], ah[ks][1], ah[ks][2], ah[ks][3], bh0, bh1);
            mma_bf16(acc[nt][0], acc[nt][1], acc[nt][2], acc[nt][3],
                     ah[ks][0], ah[ks][1], ah[ks][2], ah[ks][3], bl0, bl1);
            mma_bf16(acc[nt][0], acc[nt][1], acc[nt][2], acc[nt][3],
                     al[ks][0], al[ks][1], al[ks][2], al[ks][3], bh0, bh1);
        }
    }

    float bb0 = Wb[c], bb1 = Wb[c + 8];
    float s0 = 0.f, q0 = 0.f, s1 = 0.f, q1 = 0.f;
#pragma unroll
    for (int nt = 0; nt < 8; nt++) {
        int n = n0 + 8 * nt + 2 * qcol;
        float v0 = acc[nt][0] + bb0, v1 = acc[nt][1] + bb0;
        float v2 = acc[nt][2] + bb1, v3 = acc[nt][3] + bb1;
        s0 += v0 + v1; q0 += v0 * v0 + v1 * v1;
        s1 += v2 + v3; q1 += v2 * v2 + v3 * v3;
        *(float2*)(d_WY + ((size_t)b * CN + c) * HWN + n)     = make_float2(v0, v1);
        *(float2*)(d_WY + ((size_t)b * CN + c + 8) * HWN + n) = make_float2(v2, v3);
    }
    s0 += __shfl_xor_sync(0xffffffffu, s0, 1);
    s0 += __shfl_xor_sync(0xffffffffu, s0, 2);
    q0 += __shfl_xor_sync(0xffffffffu, q0, 1);
    q0 += __shfl_xor_sync(0xffffffffu, q0, 2);
    s1 += __shfl_xor_sync(0xffffffffu, s1, 1);
    s1 += __shfl_xor_sync(0xffffffffu, s1, 2);
    q1 += __shfl_xor_sync(0xffffffffu, q1, 1);
    q1 += __shfl_xor_sync(0xffffffffu, q1, 2);
    if (qcol == 0) {
        gPS[c * 256 + part] = s0;
        gPQ[c * 256 + part] = q0;
        gPS[(c + 8) * 256 + part] = s1;
        gPQ[(c + 8) * 256 + part] = q1;
    }
}

// ============================================================================
// K4: BN stats finalize
// ============================================================================
__global__ void bnfinal_kernel()
{
    const int c = blockIdx.x;
    const int tid = threadIdx.x;
    __shared__ float sh[256], sh2[256];
    sh[tid]  = gPS[c * 256 + tid];
    sh2[tid] = gPQ[c * 256 + tid];
    __syncthreads();
    for (int off = 128; off > 0; off >>= 1) {
        if (tid < off) { sh[tid] += sh[tid + off]; sh2[tid] += sh2[tid + off]; }
        __syncthreads();
    }
    if (tid == 0) {
        const float invN = 1.f / (float)(BN * HWN);
        float mean = sh[0] * invN;
        float var  = sh2[0] * invN - mean * mean;
        d_MEAN[c] = mean;
        d_RSTD[c] = rsqrtf(var + 1e-5f);
    }
}

// ============================================================================
// K5: finalize
// ============================================================================
__global__ void finalize_kernel(const float* __restrict__ x,
                                const float* __restrict__ gamma,
                                const float* __restrict__ beta,
                                float* __restrict__ out)
{
    int idx = blockIdx.x * blockDim.x + threadIdx.x;
    int c = (idx >> 10) & 255;
    float4 wv = ((const float4*)d_WY)[idx];
    float4 xv = ((const float4*)x)[idx];
    float g  = gamma[c] * d_RSTD[c];
    float m  = d_MEAN[c];
    float bt = beta[c];
    float4 o;
    o.x = (wv.x - m) * g + bt + xv.x;
    o.y = (wv.y - m) * g + bt + xv.y;
    o.z = (wv.z - m) * g + bt + xv.z;
    o.w = (wv.w - m) * g + bt + xv.w;
    ((float4*)out)[idx] = o;
}

// ============================================================================
extern "C" void kernel_launch(void* const* d_in, const int* in_sizes, int n_in,
                              void* d_out, int out_size)
{
    const float* x     = (const float*)d_in[0];
    const float* tw    = (const float*)d_in[1];
    const float* tb    = (const float*)d_in[2];
    const float* pw    = (const float*)d_in[3];
    const float* pb    = (const float*)d_in[4];
    const float* gw    = (const float*)d_in[5];
    const float* gb    = (const float*)d_in[6];
    const float* Ww    = (const float*)d_in[7];
    const float* Wb    = (const float*)d_in[8];
    const float* gamma = (const float*)d_in[9];
    const float* beta  = (const float*)d_in[10];
    float* out = (float*)d_out;

    cudaFuncSetAttribute(proj_mma_kernel, cudaFuncAttributeMaxDynamicSharedMemorySize, PRJ_SMEM);
    cudaFuncSetAttribute(attn_mma_kernel, cudaFuncAttributeMaxDynamicSharedMemorySize, ATTN_SMEM);
    cudaFuncSetAttribute(wgemm_mma_kernel, cudaFuncAttributeMaxDynamicSharedMemorySize, WG_SMEM);

    wsplit_kernel<<<256, 256>>>(tw, pw, gw, Ww);

    dim3 gx(HWN / 64, CN / 64, BN);
    xsplit_kernel<<<gx, 256>>>(x);

    dim3 g1(3, HWN / 64, BN);
    proj_mma_kernel<<<g1, 256, PRJ_SMEM>>>(tb, pb, gb);

    dim3 g2(HWN / TM, BN);
    attn_mma_kernel<<<g2, 256, ATTN_SMEM>>>();

    dim3 g3(2, HWN / 64, BN);
    wgemm_mma_kernel<<<g3, 256, WG_SMEM>>>(Wb);

    bnfinal_kernel<<<CN, 256>>>();

    finalize_kernel<<<(BN * CN * HWN / 4) / 256, 256>>>(x, gamma, beta, out);
}

// round 12
// speedup vs baseline: 1.1293x; 1.1293x over previous
#include <cuda_runtime.h>
#include <cuda_bf16.h>
#include <cuda_fp16.h>
#include <math.h>
#include <stdint.h>

#define BN   4
#define CN   256
#define HWN  4096
#define DN   128
#define TM   128            // queries per CTA (attention)
#define TN   64             // keys per tile
#define LOG2E 1.4426950408889634f

// attention smem stage layout (bytes)
#define K_ROW   272
#define V_ROW   144
#define KH_OFF  0
#define KL_OFF  (64 * K_ROW)
#define VH_OFF  (2 * 64 * K_ROW)
#define VL_OFF  (2 * 64 * K_ROW + 128 * V_ROW)
#define STG_SZ  (2 * 64 * K_ROW + 2 * 128 * V_ROW)   // 71680
#define ATTN_SMEM (2 * STG_SZ)                        // 143360

// proj smem (bytes): x planes [64][144B], w planes [128][144B]
#define PXH 0
#define PXL 9216
#define PWH 18432
#define PWL 36864
#define PRJ_SMEM 55296

// wgemm smem: y planes [64][272B]
#define WYH 0
#define WYL 17408
#define WG_SMEM 34816

// -------------------- scratch --------------------
__device__ __align__(128) __nv_bfloat16 gXh[BN * HWN * CN];  // x^T hi [b][n][c]
__device__ __align__(128) __nv_bfloat16 gXl[BN * HWN * CN];
__device__ __align__(128) __nv_bfloat16 gWh[3 * DN * CN];    // proj weights hi [p][i][c]
__device__ __align__(128) __nv_bfloat16 gWl[3 * DN * CN];
__device__ __align__(128) __nv_bfloat16 gWWh[CN * DN];       // W hi [c][i]
__device__ __align__(128) __nv_bfloat16 gWWl[CN * DN];
__device__ __align__(128) __nv_bfloat16 gQh[BN * HWN * DN];  // theta hi [b][n][k]
__device__ __align__(128) __nv_bfloat16 gQl[BN * HWN * DN];
__device__ __align__(128) __nv_bfloat16 gKh[BN * HWN * DN];  // phi(scaled) hi [b][m][k]
__device__ __align__(128) __nv_bfloat16 gKl[BN * HWN * DN];
__device__ __align__(128) __half gVh[BN * DN * HWN];         // g hi (fp16) [b][d][m]
__device__ __align__(128) __half gVl[BN * DN * HWN];         // g lo (fp16)
__device__ __align__(128) __nv_bfloat16 gYh[BN * HWN * DN];  // attn out hi [b][n][i]
__device__ __align__(128) __nv_bfloat16 gYl[BN * HWN * DN];
__device__ __align__(128) float d_WY[BN * CN * HWN];         // [b][c][n]
__device__ float gPS[CN * 256];
__device__ float gPQ[CN * 256];
__device__ float d_MEAN[CN];
__device__ float d_RSTD[CN];

// ======================= helpers =======================
__device__ __forceinline__ uint32_t smem_u32(const void* p) {
    uint32_t a;
    asm("{ .reg .u64 t; cvta.to.shared.u64 t, %1; cvt.u32.u64 %0, t; }" : "=r"(a) : "l"(p));
    return a;
}
__device__ __forceinline__ void cp16(uint32_t dst, const void* src) {
    asm volatile("cp.async.cg.shared.global [%0], [%1], 16;" :: "r"(dst), "l"(src));
}
#define CP_COMMIT() asm volatile("cp.async.commit_group;" ::: "memory")
#define CP_WAIT0()  asm volatile("cp.async.wait_group 0;" ::: "memory")
#define CP_WAIT1()  asm volatile("cp.async.wait_group 1;" ::: "memory")

__device__ __forceinline__ void mma_bf16(float& c0, float& c1, float& c2, float& c3,
                                         uint32_t a0, uint32_t a1, uint32_t a2, uint32_t a3,
                                         uint32_t b0, uint32_t b1) {
    asm volatile("mma.sync.aligned.m16n8k16.row.col.f32.bf16.bf16.f32 "
                 "{%0,%1,%2,%3}, {%4,%5,%6,%7}, {%8,%9}, {%0,%1,%2,%3};"
                 : "+f"(c0), "+f"(c1), "+f"(c2), "+f"(c3)
                 : "r"(a0), "r"(a1), "r"(a2), "r"(a3), "r"(b0), "r"(b1));
}
__device__ __forceinline__ void mma_f16(float& c0, float& c1, float& c2, float& c3,
                                        uint32_t a0, uint32_t a1, uint32_t a2, uint32_t a3,
                                        uint32_t b0, uint32_t b1) {
    asm volatile("mma.sync.aligned.m16n8k16.row.col.f32.f16.f16.f32 "
                 "{%0,%1,%2,%3}, {%4,%5,%6,%7}, {%8,%9}, {%0,%1,%2,%3};"
                 : "+f"(c0), "+f"(c1), "+f"(c2), "+f"(c3)
                 : "r"(a0), "r"(a1), "r"(a2), "r"(a3), "r"(b0), "r"(b1));
}
__device__ __forceinline__ uint32_t lds32(uint32_t addr) {
    uint32_t v;
    asm volatile("ld.shared.b32 %0, [%1];" : "=r"(v) : "r"(addr));
    return v;
}
__device__ __forceinline__ float ex2(float x) {
    float y;
    asm("ex2.approx.ftz.f32 %0, %1;" : "=f"(y) : "f"(x));
    return y;
}
__device__ __forceinline__ void split2(float v0, float v1, uint32_t& hi, uint32_t& lo) {
    __nv_bfloat16 h0 = __float2bfloat16(v0);
    __nv_bfloat16 h1 = __float2bfloat16(v1);
    float r0 = v0 - __bfloat162float(h0);
    float r1 = v1 - __bfloat162float(h1);
    __nv_bfloat162 hh; hh.x = h0; hh.y = h1;
    __nv_bfloat162 ll; ll.x = __float2bfloat16(r0); ll.y = __float2bfloat16(r1);
    hi = *(uint32_t*)&hh;
    lo = *(uint32_t*)&ll;
}
__device__ __forceinline__ void split2h(float v0, float v1, uint32_t& hi, uint32_t& lo) {
    __half h0 = __float2half_rn(v0);
    __half h1 = __float2half_rn(v1);
    float r0 = v0 - __half2float(h0);
    float r1 = v1 - __half2float(h1);
    __half2 hh; hh.x = h0; hh.y = h1;
    __half2 ll; ll.x = __float2half_rn(r0); ll.y = __float2half_rn(r1);
    hi = *(uint32_t*)&hh;
    lo = *(uint32_t*)&ll;
}
__device__ __forceinline__ uint32_t pack_h2(float v0, float v1) {
    __half2 h = __floats2half2_rn(v0, v1);
    return *(uint32_t*)&h;
}
__device__ __forceinline__ void split1(float v, unsigned short& h, unsigned short& l) {
    __nv_bfloat16 hb = __float2bfloat16(v);
    float r = v - __bfloat162float(hb);
    __nv_bfloat16 lb = __float2bfloat16(r);
    h = *(unsigned short*)&hb;
    l = *(unsigned short*)&lb;
}

// ============================================================================
// K0: pre-split all weights to bf16 hi/lo.
// ============================================================================
__global__ void wsplit_kernel(const float* __restrict__ tw, const float* __restrict__ pw,
                              const float* __restrict__ gw, const float* __restrict__ Ww)
{
    int idx = blockIdx.x * 256 + threadIdx.x;
    if (idx < 49152) {
        int p = idx / 16384, r = idx - p * 16384;
        const float* s = (p == 0) ? tw : (p == 1) ? pw : gw;
        float2 v = *(const float2*)(s + 2 * r);
        uint32_t hi, lo;
        split2(v.x, v.y, hi, lo);
        *(uint32_t*)(gWh + p * 32768 + 2 * r) = hi;
        *(uint32_t*)(gWl + p * 32768 + 2 * r) = lo;
    } else {
        int r = idx - 49152;
        float2 v = *(const float2*)(Ww + 2 * r);
        uint32_t hi, lo;
        split2(v.x, v.y, hi, lo);
        *(uint32_t*)(gWWh + 2 * r) = hi;
        *(uint32_t*)(gWWl + 2 * r) = lo;
    }
}

// ============================================================================
// K0b: transpose+split x -> xT hi/lo [b][n][c].
// ============================================================================
__global__ void xsplit_kernel(const float* __restrict__ x)
{
    __shared__ float xs[64][68];
    const int n0 = blockIdx.x * 64;
    const int c0 = blockIdx.y * 64;
    const int b  = blockIdx.z;
    const int tid = threadIdx.x;
#pragma unroll
    for (int r = 0; r < 4; r++) {
        int fid = tid + (r << 8);
        int cc = fid >> 4, n4 = fid & 15;
        float4 v = *(const float4*)(x + ((size_t)b * CN + c0 + cc) * HWN + n0 + 4 * n4);
        *(float4*)&xs[cc][4 * n4] = v;
    }
    __syncthreads();
#pragma unroll
    for (int r = 0; r < 8; r++) {
        int fid = tid + (r << 8);
        int n = fid >> 5, cp = fid & 31;
        float a  = xs[2 * cp][n];
        float bb = xs[2 * cp + 1][n];
        uint32_t hi, lo;
        split2(a, bb, hi, lo);
        size_t gi = ((size_t)b * HWN + n0 + n) * CN + c0 + 2 * cp;
        *(uint32_t*)(gXh + gi) = hi;
        *(uint32_t*)(gXl + gi) = lo;
    }
}

// ============================================================================
// K1: projections via mma.sync (pre-split operands).
// ============================================================================
__global__ void __launch_bounds__(256) proj_mma_kernel(
    const float* __restrict__ tb, const float* __restrict__ pb, const float* __restrict__ gb)
{
    extern __shared__ char psm[];
    const uint32_t smb = smem_u32(psm);
    unsigned short* sth = (unsigned short*)(psm);            // stage hi [64][130]
    unsigned short* stl = (unsigned short*)(psm + 16640);    // stage lo [64][130]

    const int p  = blockIdx.x;
    const int n0 = blockIdx.y * 64;
    const int b  = blockIdx.z;
    const float* bias = (p == 0) ? tb : (p == 1) ? pb : gb;

    const int tid  = threadIdx.x;
    const int wrp  = tid >> 5;
    const int lane = tid & 31;
    const int qrow = lane >> 2;
    const int qcol = lane & 3;
    const int i0   = 16 * wrp + qrow;

    float acc[8][4];
#pragma unroll
    for (int i = 0; i < 8; i++)
#pragma unroll
        for (int j = 0; j < 4; j++) acc[i][j] = 0.f;

    for (int c0 = 0; c0 < CN; c0 += 64) {
        __syncthreads();
#pragma unroll
        for (int r = 0; r < 4; r++) {
            int fid = tid + (r << 8);
            int pl = fid >> 9, rem = fid & 511;
            int row = rem >> 3, ch = rem & 7;
            const __nv_bfloat16* src = (pl ? gXl : gXh) +
                ((size_t)b * HWN + n0 + row) * CN + c0 + ch * 8;
            cp16(smb + (pl ? PXL : PXH) + row * 144 + ch * 16, src);
        }
#pragma unroll
        for (int r = 0; r < 8; r++) {
            int fid = tid + (r << 8);
            int pl = fid >> 10, rem = fid & 1023;
            int row = rem >> 3, ch = rem & 7;
            const __nv_bfloat16* src = (pl ? gWl : gWh) +
                (size_t)p * 32768 + row * CN + c0 + ch * 8;
            cp16(smb + (pl ? PWL : PWH) + row * 144 + ch * 16, src);
        }
        CP_COMMIT();
        CP_WAIT0();
        __syncthreads();

        uint32_t ah[4][4], al[4][4];
#pragma unroll
        for (int ks = 0; ks < 4; ks++) {
            uint32_t ko = 32 * ks + 4 * qcol;
            ah[ks][0] = lds32(smb + PWH + i0 * 144 + ko);
            ah[ks][1] = lds32(smb + PWH + (i0 + 8) * 144 + ko);
            ah[ks][2] = lds32(smb + PWH + i0 * 144 + ko + 16);
            ah[ks][3] = lds32(smb + PWH + (i0 + 8) * 144 + ko + 16);
            al[ks][0] = lds32(smb + PWL + i0 * 144 + ko);
            al[ks][1] = lds32(smb + PWL + (i0 + 8) * 144 + ko);
            al[ks][2] = lds32(smb + PWL + i0 * 144 + ko + 16);
            al[ks][3] = lds32(smb + PWL + (i0 + 8) * 144 + ko + 16);
        }
#pragma unroll
        for (int ks = 0; ks < 4; ks++) {
#pragma unroll
            for (int nt = 0; nt < 8; nt++) {
                uint32_t ro = (8 * nt + qrow) * 144 + 32 * ks + 4 * qcol;
                uint32_t bh0 = lds32(smb + PXH + ro);
                uint32_t bh1 = lds32(smb + PXH + ro + 16);
                uint32_t bl0 = lds32(smb + PXL + ro);
                uint32_t bl1 = lds32(smb + PXL + ro + 16);
                mma_bf16(acc[nt][0], acc[nt][1], acc[nt][2], acc[nt][3],
                         ah[ks][0], ah[ks][1], ah[ks][2], ah[ks][3], bh0, bh1);
                mma_bf16(acc[nt][0], acc[nt][1], acc[nt][2], acc[nt][3],
                         ah[ks][0], ah[ks][1], ah[ks][2], ah[ks][3], bl0, bl1);
                mma_bf16(acc[nt][0], acc[nt][1], acc[nt][2], acc[nt][3],
                         al[ks][0], al[ks][1], al[ks][2], al[ks][3], bh0, bh1);
            }
        }
    }

    const float bb0 = bias[i0];
    const float bb1 = bias[i0 + 8];
    const float sc  = (p == 1) ? LOG2E : 1.f;

    if (p < 2) {
        __syncthreads();
#pragma unroll
        for (int nt = 0; nt < 8; nt++) {
            int n = 8 * nt + 2 * qcol;
            float v0 = (acc[nt][0] + bb0) * sc, v1 = (acc[nt][1] + bb0) * sc;
            float v2 = (acc[nt][2] + bb1) * sc, v3 = (acc[nt][3] + bb1) * sc;
            unsigned short h, l;
            split1(v0, h, l); sth[n * 130 + i0] = h;           stl[n * 130 + i0] = l;
            split1(v1, h, l); sth[(n + 1) * 130 + i0] = h;     stl[(n + 1) * 130 + i0] = l;
            split1(v2, h, l); sth[n * 130 + i0 + 8] = h;       stl[n * 130 + i0 + 8] = l;
            split1(v3, h, l); sth[(n + 1) * 130 + i0 + 8] = h; stl[(n + 1) * 130 + i0 + 8] = l;
        }
        __syncthreads();
        __nv_bfloat16* oh = (p == 0) ? gQh : gKh;
        __nv_bfloat16* ol = (p == 0) ? gQl : gKl;
#pragma unroll
        for (int r = 0; r < 16; r++) {
            int t = tid + (r << 8);
            int row = t >> 6, w32 = t & 63;
            uint32_t hv = *(uint32_t*)&sth[row * 130 + 2 * w32];
            uint32_t lv = *(uint32_t*)&stl[row * 130 + 2 * w32];
            size_t gb_ = ((size_t)b * HWN + n0 + row) * DN + 2 * w32;
            *(uint32_t*)(oh + gb_) = hv;
            *(uint32_t*)(ol + gb_) = lv;
        }
    } else {
        // g -> fp16 hi/lo planes [b][d][m]
#pragma unroll
        for (int nt = 0; nt < 8; nt++) {
            int n = n0 + 8 * nt + 2 * qcol;
            float v0 = acc[nt][0] + bb0, v1 = acc[nt][1] + bb0;
            float v2 = acc[nt][2] + bb1, v3 = acc[nt][3] + bb1;
            uint32_t h01, l01, h23, l23;
            split2h(v0, v1, h01, l01);
            split2h(v2, v3, h23, l23);
            size_t ba = ((size_t)b * DN + i0) * HWN + n;
            size_t bc = ((size_t)b * DN + i0 + 8) * HWN + n;
            *(uint32_t*)(gVh + ba) = h01;
            *(uint32_t*)(gVl + ba) = l01;
            *(uint32_t*)(gVh + bc) = h23;
            *(uint32_t*)(gVl + bc) = l23;
        }
    }
}

// ============================================================================
// K2: flash attention — bf16 split-2 S (3 terms), fp16 single-plane P with
//     per-tile running max, fp16 split-2 V => PV in 2 terms (320 HMMA/tile).
// ============================================================================
__device__ __forceinline__ void load_kv_tile(uint32_t stg, int b, int m0, int tid) {
#pragma unroll
    for (int r = 0; r < 4; r++) {
        int ch = tid + (r << 8);
        int rw = ch >> 4;
        int kc = ch & 15;
        uint32_t dst = stg + rw * K_ROW + (kc << 4);
        size_t gi = (((size_t)b * HWN + m0 + rw) << 7) + (kc << 3);
        cp16(dst + KH_OFF, gKh + gi);
        cp16(dst + KL_OFF, gKl + gi);
    }
#pragma unroll
    for (int r = 0; r < 4; r++) {
        int ch = tid + (r << 8);
        int rw = ch >> 3;
        int mc = ch & 7;
        uint32_t dst = stg + rw * V_ROW + (mc << 4);
        size_t gi = (((size_t)b * DN + rw) << 12) + m0 + (mc << 3);
        cp16(dst + VH_OFF, gVh + gi);
        cp16(dst + VL_OFF, gVl + gi);
    }
}

__global__ void __launch_bounds__(256, 1) attn_mma_kernel()
{
    extern __shared__ char smem[];
    const uint32_t smb = smem_u32(smem);

    const int tid  = threadIdx.x;
    const int lane = tid & 31;
    const int wrp  = tid >> 5;
    const int qrow = lane >> 2;
    const int qcol = lane & 3;
    const int n0   = blockIdx.x * TM;
    const int b    = blockIdx.y;
    const int row0 = 16 * wrp + qrow;

    uint32_t qh[8][4], ql[8][4];
    {
        const size_t rbase = ((size_t)b * HWN + n0 + row0) * DN;
#pragma unroll
        for (int ks = 0; ks < 8; ks++) {
            int k0 = 16 * ks + 2 * qcol;
            qh[ks][0] = *(const uint32_t*)(gQh + rbase + k0);
            qh[ks][1] = *(const uint32_t*)(gQh + rbase + 8 * DN + k0);
            qh[ks][2] = *(const uint32_t*)(gQh + rbase + k0 + 8);
            qh[ks][3] = *(const uint32_t*)(gQh + rbase + 8 * DN + k0 + 8);
            ql[ks][0] = *(const uint32_t*)(gQl + rbase + k0);
            ql[ks][1] = *(const uint32_t*)(gQl + rbase + 8 * DN + k0);
            ql[ks][2] = *(const uint32_t*)(gQl + rbase + k0 + 8);
            ql[ks][3] = *(const uint32_t*)(gQl + rbase + 8 * DN + k0 + 8);
        }
    }

    float o[16][4];
#pragma unroll
    for (int i = 0; i < 16; i++)
#pragma unroll
        for (int j = 0; j < 4; j++) o[i][j] = 0.f;

    float rs0 = 0.f, rs1 = 0.f;
    float m0 = -INFINITY, m1 = -INFINITY;

    load_kv_tile(smb, b, 0, tid);
    CP_COMMIT();

    for (int t = 0; t < 64; t++) {
        const uint32_t stg = smb + (uint32_t)(t & 1) * STG_SZ;
        __syncthreads();
        if (t + 1 < 64) {
            load_kv_tile(smb + (uint32_t)((t + 1) & 1) * STG_SZ, b, (t + 1) * TN, tid);
            CP_COMMIT();
            CP_WAIT1();
        } else {
            CP_WAIT0();
        }
        __syncthreads();

        // ---- S = Q K^T (bf16, 3 terms), R7 structure ----
        float cA[8][4];
#pragma unroll
        for (int nt = 0; nt < 8; nt++) {
            float c0 = 0.f, c1 = 0.f, c2 = 0.f, c3 = 0.f;
            const uint32_t krow = stg + (uint32_t)(8 * nt + qrow) * K_ROW + (uint32_t)(4 * qcol);
#pragma unroll
            for (int ks = 0; ks < 8; ks++) {
                uint32_t bh0 = lds32(krow + KH_OFF + 32 * ks);
                uint32_t bh1 = lds32(krow + KH_OFF + 32 * ks + 16);
                uint32_t bl0 = lds32(krow + KL_OFF + 32 * ks);
                uint32_t bl1 = lds32(krow + KL_OFF + 32 * ks + 16);
                mma_bf16(c0, c1, c2, c3, qh[ks][0], qh[ks][1], qh[ks][2], qh[ks][3], bh0, bh1);
                mma_bf16(c0, c1, c2, c3, qh[ks][0], qh[ks][1], qh[ks][2], qh[ks][3], bl0, bl1);
                mma_bf16(c0, c1, c2, c3, ql[ks][0], ql[ks][1], ql[ks][2], ql[ks][3], bh0, bh1);
            }
            cA[nt][0] = c0; cA[nt][1] = c1; cA[nt][2] = c2; cA[nt][3] = c3;
        }

        // ---- per-tile row max (exp2 domain), running-max rescale ----
        float mx0 = cA[0][0], mx1 = cA[0][2];
#pragma unroll
        for (int nt = 0; nt < 8; nt++) {
            mx0 = fmaxf(mx0, fmaxf(cA[nt][0], cA[nt][1]));
            mx1 = fmaxf(mx1, fmaxf(cA[nt][2], cA[nt][3]));
        }
        mx0 = fmaxf(mx0, __shfl_xor_sync(0xffffffffu, mx0, 1));
        mx0 = fmaxf(mx0, __shfl_xor_sync(0xffffffffu, mx0, 2));
        mx1 = fmaxf(mx1, __shfl_xor_sync(0xffffffffu, mx1, 1));
        mx1 = fmaxf(mx1, __shfl_xor_sync(0xffffffffu, mx1, 2));
        float mn0 = fmaxf(m0, mx0);
        float mn1 = fmaxf(m1, mx1);
        float a0 = ex2(m0 - mn0);       // 0 on first tile (m=-inf), else <=1
        float a1 = ex2(m1 - mn1);
        m0 = mn0; m1 = mn1;
        rs0 *= a0; rs1 *= a1;
#pragma unroll
        for (int nt = 0; nt < 16; nt++) {
            o[nt][0] *= a0; o[nt][1] *= a0;
            o[nt][2] *= a1; o[nt][3] *= a1;
        }

        // ---- p = 2^(f - m) in fp16 (single plane) ----
        uint32_t ph[8][2];
#pragma unroll
        for (int nt = 0; nt < 8; nt++) {
            float e0 = ex2(cA[nt][0] - m0), e1 = ex2(cA[nt][1] - m0);
            float e2 = ex2(cA[nt][2] - m1), e3 = ex2(cA[nt][3] - m1);
            rs0 += e0 + e1;
            rs1 += e2 + e3;
            ph[nt][0] = pack_h2(e0, e1);
            ph[nt][1] = pack_h2(e2, e3);
        }

        // ---- O += P V (fp16, 2 terms) ----
#pragma unroll
        for (int ks = 0; ks < 4; ks++) {
            uint32_t ah0 = ph[2 * ks][0], ah1 = ph[2 * ks][1];
            uint32_t ah2 = ph[2 * ks + 1][0], ah3 = ph[2 * ks + 1][1];
            const uint32_t vcol = stg + (uint32_t)(32 * ks + 4 * qcol);
#pragma unroll
            for (int nt = 0; nt < 16; nt++) {
                const uint32_t vrow = vcol + (uint32_t)(8 * nt + qrow) * V_ROW;
                uint32_t bh0 = lds32(vrow + VH_OFF);
                uint32_t bh1 = lds32(vrow + VH_OFF + 16);
                uint32_t bl0 = lds32(vrow + VL_OFF);
                uint32_t bl1 = lds32(vrow + VL_OFF + 16);
                mma_f16(o[nt][0], o[nt][1], o[nt][2], o[nt][3], ah0, ah1, ah2, ah3, bh0, bh1);
                mma_f16(o[nt][0], o[nt][1], o[nt][2], o[nt][3], ah0, ah1, ah2, ah3, bl0, bl1);
            }
        }
    }

    rs0 += __shfl_xor_sync(0xffffffffu, rs0, 1);
    rs0 += __shfl_xor_sync(0xffffffffu, rs0, 2);
    rs1 += __shfl_xor_sync(0xffffffffu, rs1, 1);
    rs1 += __shfl_xor_sync(0xffffffffu, rs1, 2);
    float inv0 = 1.f / rs0;
    float inv1 = 1.f / rs1;

    const size_t y0 = ((size_t)b * HWN + n0 + row0) * DN + 2 * qcol;
    const size_t y1 = y0 + 8 * DN;
#pragma unroll
    for (int nt = 0; nt < 16; nt++) {
        uint32_t h0, l0, h1, l1;
        split2(o[nt][0] * inv0, o[nt][1] * inv0, h0, l0);
        split2(o[nt][2] * inv1, o[nt][3] * inv1, h1, l1);
        *(uint32_t*)(gYh + y0 + 8 * nt) = h0;
        *(uint32_t*)(gYl + y0 + 8 * nt) = l0;
        *(uint32_t*)(gYh + y1 + 8 * nt) = h1;
        *(uint32_t*)(gYl + y1 + 8 * nt) = l1;
    }
}

// ============================================================================
// K3: wy = W*y + b via mma.sync, operands pre-split; fused BN partials.
// ============================================================================
__global__ void __launch_bounds__(256) wgemm_mma_kernel(const float* __restrict__ Wb)
{
    extern __shared__ char wsm[];
    const uint32_t smb = smem_u32(wsm);

    const int c0 = blockIdx.x * 128;
    const int n0 = blockIdx.y * 64;
    const int b  = blockIdx.z;
    const int part = blockIdx.y * 4 + blockIdx.z;

    const int tid  = threadIdx.x;
    const int lane = tid & 31;
    const int wrp  = tid >> 5;
    const int qrow = lane >> 2;
    const int qcol = lane & 3;
    const int c    = c0 + 16 * wrp + qrow;

#pragma unroll
    for (int r = 0; r < 8; r++) {
        int fid = tid + (r << 8);
        int pl = fid >> 10, rem = fid & 1023;
        int row = rem >> 4, ch = rem & 15;
        const __nv_bfloat16* src = (pl ? gYl : gYh) +
            ((size_t)b * HWN + n0 + row) * DN + ch * 8;
        cp16(smb + (pl ? WYL : WYH) + row * 272 + ch * 16, src);
    }
    CP_COMMIT();

    uint32_t ah[8][4], al[8][4];
#pragma unroll
    for (int ks = 0; ks < 8; ks++) {
        int k = 16 * ks + 2 * qcol;
        ah[ks][0] = *(const uint32_t*)(gWWh + (size_t)c * DN + k);
        ah[ks][1] = *(const uint32_t*)(gWWh + (size_t)(c + 8) * DN + k);
        ah[ks][2] = *(const uint32_t*)(gWWh + (size_t)c * DN + k + 8);
        ah[ks][3] = *(const uint32_t*)(gWWh + (size_t)(c + 8) * DN + k + 8);
        al[ks][0] = *(const uint32_t*)(gWWl + (size_t)c * DN + k);
        al[ks][1] = *(const uint32_t*)(gWWl + (size_t)(c + 8) * DN + k);
        al[ks][2] = *(const uint32_t*)(gWWl + (size_t)c * DN + k + 8);
        al[ks][3] = *(const uint32_t*)(gWWl + (size_t)(c + 8) * DN + k + 8);
    }
    CP_WAIT0();
    __syncthreads();

    float acc[8][4];
#pragma unroll
    for (int i = 0; i < 8; i++)
#pragma unroll
        for (int j = 0; j < 4; j++) acc[i][j] = 0.f;

#pragma unroll
    for (int ks = 0; ks < 8; ks++) {
#pragma unroll
        for (int nt = 0; nt < 8; nt++) {
            uint32_t ro = (8 * nt + qrow) * 272 + 32 * ks + 4 * qcol;
            uint32_t bh0 = lds32(smb + WYH + ro);
            uint32_t bh1 = lds32(smb + WYH + ro + 16);
            uint32_t bl0 = lds32(smb + WYL + ro);
            uint32_t bl1 = lds32(smb + WYL + ro + 16);
            mma_bf16(acc[nt][0], acc[nt][1], acc[nt][2], acc[nt][3],
                     ah[ks][0], ah[ks][1], ah[ks][2], ah[ks][3], bh0, bh1);
            mma_bf16(acc[nt][0], acc[nt][1], acc[nt][2], acc[nt][3],
                     ah[ks][0], ah[ks][1], ah[ks][2], ah[ks][3], bl0, bl1);
            mma_bf16(acc[nt][0], acc[nt][1], acc[nt][2], acc[nt][3],
                     al[ks][0], al[ks][1], al[ks][2], al[ks][3], bh0, bh1);
        }
    }

    float bb0 = Wb[c], bb1 = Wb[c + 8];
    float s0 = 0.f, q0 = 0.f, s1 = 0.f, q1 = 0.f;
#pragma unroll
    for (int nt = 0; nt < 8; nt++) {
        int n = n0 + 8 * nt + 2 * qcol;
        float v0 = acc[nt][0] + bb0, v1 = acc[nt][1] + bb0;
        float v2 = acc[nt][2] + bb1, v3 = acc[nt][3] + bb1;
        s0 += v0 + v1; q0 += v0 * v0 + v1 * v1;
        s1 += v2 + v3; q1 += v2 * v2 + v3 * v3;
        *(float2*)(d_WY + ((size_t)b * CN + c) * HWN + n)     = make_float2(v0, v1);
        *(float2*)(d_WY + ((size_t)b * CN + c + 8) * HWN + n) = make_float2(v2, v3);
    }
    s0 += __shfl_xor_sync(0xffffffffu, s0, 1);
    s0 += __shfl_xor_sync(0xffffffffu, s0, 2);
    q0 += __shfl_xor_sync(0xffffffffu, q0, 1);
    q0 += __shfl_xor_sync(0xffffffffu, q0, 2);
    s1 += __shfl_xor_sync(0xffffffffu, s1, 1);
    s1 += __shfl_xor_sync(0xffffffffu, s1, 2);
    q1 += __shfl_xor_sync(0xffffffffu, q1, 1);
    q1 += __shfl_xor_sync(0xffffffffu, q1, 2);
    if (qcol == 0) {
        gPS[c * 256 + part] = s0;
        gPQ[c * 256 + part] = q0;
        gPS[(c + 8) * 256 + part] = s1;
        gPQ[(c + 8) * 256 + part] = q1;
    }
}

// ============================================================================
// K4: BN stats finalize
// ============================================================================
__global__ void bnfinal_kernel()
{
    const int c = blockIdx.x;
    const int tid = threadIdx.x;
    __shared__ float sh[256], sh2[256];
    sh[tid]  = gPS[c * 256 + tid];
    sh2[tid] = gPQ[c * 256 + tid];
    __syncthreads();
    for (int off = 128; off > 0; off >>= 1) {
        if (tid < off) { sh[tid] += sh[tid + off]; sh2[tid] += sh2[tid + off]; }
        __syncthreads();
    }
    if (tid == 0) {
        const float invN = 1.f / (float)(BN * HWN);
        float mean = sh[0] * invN;
        float var  = sh2[0] * invN - mean * mean;
        d_MEAN[c] = mean;
        d_RSTD[c] = rsqrtf(var + 1e-5f);
    }
}

// ============================================================================
// K5: finalize
// ============================================================================
__global__ void finalize_kernel(const float* __restrict__ x,
                                const float* __restrict__ gamma,
                                const float* __restrict__ beta,
                                float* __restrict__ out)
{
    int idx = blockIdx.x * blockDim.x + threadIdx.x;
    int c = (idx >> 10) & 255;
    float4 wv = ((const float4*)d_WY)[idx];
    float4 xv = ((const float4*)x)[idx];
    float g  = gamma[c] * d_RSTD[c];
    float m  = d_MEAN[c];
    float bt = beta[c];
    float4 o;
    o.x = (wv.x - m) * g + bt + xv.x;
    o.y = (wv.y - m) * g + bt + xv.y;
    o.z = (wv.z - m) * g + bt + xv.z;
    o.w = (wv.w - m) * g + bt + xv.w;
    ((float4*)out)[idx] = o;
}

// ============================================================================
extern "C" void kernel_launch(void* const* d_in, const int* in_sizes, int n_in,
                              void* d_out, int out_size)
{
    const float* x     = (const float*)d_in[0];
    const float* tw    = (const float*)d_in[1];
    const float* tb    = (const float*)d_in[2];
    const float* pw    = (const float*)d_in[3];
    const float* pb    = (const float*)d_in[4];
    const float* gw    = (const float*)d_in[5];
    const float* gb    = (const float*)d_in[6];
    const float* Ww    = (const float*)d_in[7];
    const float* Wb    = (const float*)d_in[8];
    const float* gamma = (const float*)d_in[9];
    const float* beta  = (const float*)d_in[10];
    float* out = (float*)d_out;

    cudaFuncSetAttribute(proj_mma_kernel, cudaFuncAttributeMaxDynamicSharedMemorySize, PRJ_SMEM);
    cudaFuncSetAttribute(attn_mma_kernel, cudaFuncAttributeMaxDynamicSharedMemorySize, ATTN_SMEM);
    cudaFuncSetAttribute(wgemm_mma_kernel, cudaFuncAttributeMaxDynamicSharedMemorySize, WG_SMEM);

    wsplit_kernel<<<256, 256>>>(tw, pw, gw, Ww);

    dim3 gx(HWN / 64, CN / 64, BN);
    xsplit_kernel<<<gx, 256>>>(x);

    dim3 g1(3, HWN / 64, BN);
    proj_mma_kernel<<<g1, 256, PRJ_SMEM>>>(tb, pb, gb);

    dim3 g2(HWN / TM, BN);
    attn_mma_kernel<<<g2, 256, ATTN_SMEM>>>();

    dim3 g3(2, HWN / 64, BN);
    wgemm_mma_kernel<<<g3, 256, WG_SMEM>>>(Wb);

    bnfinal_kernel<<<CN, 256>>>();

    finalize_kernel<<<(BN * CN * HWN / 4) / 256, 256>>>(x, gamma, beta, out);
}

// round 13
// speedup vs baseline: 1.2486x; 1.1056x over previous
#include <cuda_runtime.h>
#include <cuda_bf16.h>
#include <cuda_fp16.h>
#include <math.h>
#include <stdint.h>

#define BN   4
#define CN   256
#define HWN  4096
#define DN   128
#define TM   128            // queries per CTA (attention)
#define TN   64             // keys per tile
#define LOG2E 1.4426950408889634f

// attention smem stage layout (bytes)
#define K_ROW   272
#define V_ROW   144
#define KH_OFF  0
#define KL_OFF  (64 * K_ROW)
#define VH_OFF  (2 * 64 * K_ROW)
#define VL_OFF  (2 * 64 * K_ROW + 128 * V_ROW)
#define STG_SZ  (2 * 64 * K_ROW + 2 * 128 * V_ROW)   // 71680
#define ATTN_SMEM (2 * STG_SZ)                        // 143360

// proj smem (bytes): x planes [64][144B], w planes [128][144B]
#define PXH 0
#define PXL 9216
#define PWH 18432
#define PWL 36864
#define PRJ_SMEM 55296

// wgemm smem: y planes [64][272B]
#define WYH 0
#define WYL 17408
#define WG_SMEM 34816

// -------------------- scratch --------------------
__device__ __align__(128) __nv_bfloat16 gXh[BN * HWN * CN];  // x^T hi [b][n][c]
__device__ __align__(128) __nv_bfloat16 gXl[BN * HWN * CN];
__device__ __align__(128) __nv_bfloat16 gWh[3 * DN * CN];    // proj weights hi [p][i][c]
__device__ __align__(128) __nv_bfloat16 gWl[3 * DN * CN];
__device__ __align__(128) __nv_bfloat16 gWWh[CN * DN];       // W hi [c][i]
__device__ __align__(128) __nv_bfloat16 gWWl[CN * DN];
__device__ __align__(128) __half gQh[BN * HWN * DN];         // theta fp16 [b][n][k]
__device__ __align__(128) __half gQl[BN * HWN * DN];         // (written, unused)
__device__ __align__(128) __half gKh[BN * HWN * DN];         // phi(scaled) hi fp16 [b][m][k]
__device__ __align__(128) __half gKl[BN * HWN * DN];         // phi lo fp16
__device__ __align__(128) __half gVh[BN * DN * HWN];         // g hi fp16 [b][d][m]
__device__ __align__(128) __half gVl[BN * DN * HWN];         // g lo fp16
__device__ __align__(128) __nv_bfloat16 gYh[BN * HWN * DN];  // attn out hi [b][n][i]
__device__ __align__(128) __nv_bfloat16 gYl[BN * HWN * DN];
__device__ __align__(128) float d_WY[BN * CN * HWN];         // [b][c][n]
__device__ float gPS[CN * 256];
__device__ float gPQ[CN * 256];
__device__ float d_MEAN[CN];
__device__ float d_RSTD[CN];

// ======================= helpers =======================
__device__ __forceinline__ uint32_t smem_u32(const void* p) {
    uint32_t a;
    asm("{ .reg .u64 t; cvta.to.shared.u64 t, %1; cvt.u32.u64 %0, t; }" : "=r"(a) : "l"(p));
    return a;
}
__device__ __forceinline__ void cp16(uint32_t dst, const void* src) {
    asm volatile("cp.async.cg.shared.global [%0], [%1], 16;" :: "r"(dst), "l"(src));
}
#define CP_COMMIT() asm volatile("cp.async.commit_group;" ::: "memory")
#define CP_WAIT0()  asm volatile("cp.async.wait_group 0;" ::: "memory")
#define CP_WAIT1()  asm volatile("cp.async.wait_group 1;" ::: "memory")

__device__ __forceinline__ void mma_bf16(float& c0, float& c1, float& c2, float& c3,
                                         uint32_t a0, uint32_t a1, uint32_t a2, uint32_t a3,
                                         uint32_t b0, uint32_t b1) {
    asm volatile("mma.sync.aligned.m16n8k16.row.col.f32.bf16.bf16.f32 "
                 "{%0,%1,%2,%3}, {%4,%5,%6,%7}, {%8,%9}, {%0,%1,%2,%3};"
                 : "+f"(c0), "+f"(c1), "+f"(c2), "+f"(c3)
                 : "r"(a0), "r"(a1), "r"(a2), "r"(a3), "r"(b0), "r"(b1));
}
__device__ __forceinline__ void mma_f16(float& c0, float& c1, float& c2, float& c3,
                                        uint32_t a0, uint32_t a1, uint32_t a2, uint32_t a3,
                                        uint32_t b0, uint32_t b1) {
    asm volatile("mma.sync.aligned.m16n8k16.row.col.f32.f16.f16.f32 "
                 "{%0,%1,%2,%3}, {%4,%5,%6,%7}, {%8,%9}, {%0,%1,%2,%3};"
                 : "+f"(c0), "+f"(c1), "+f"(c2), "+f"(c3)
                 : "r"(a0), "r"(a1), "r"(a2), "r"(a3), "r"(b0), "r"(b1));
}
__device__ __forceinline__ uint32_t lds32(uint32_t addr) {
    uint32_t v;
    asm volatile("ld.shared.b32 %0, [%1];" : "=r"(v) : "r"(addr));
    return v;
}
__device__ __forceinline__ float ex2(float x) {
    float y;
    asm("ex2.approx.ftz.f32 %0, %1;" : "=f"(y) : "f"(x));
    return y;
}
__device__ __forceinline__ void split2(float v0, float v1, uint32_t& hi, uint32_t& lo) {
    __nv_bfloat16 h0 = __float2bfloat16(v0);
    __nv_bfloat16 h1 = __float2bfloat16(v1);
    float r0 = v0 - __bfloat162float(h0);
    float r1 = v1 - __bfloat162float(h1);
    __nv_bfloat162 hh; hh.x = h0; hh.y = h1;
    __nv_bfloat162 ll; ll.x = __float2bfloat16(r0); ll.y = __float2bfloat16(r1);
    hi = *(uint32_t*)&hh;
    lo = *(uint32_t*)&ll;
}
__device__ __forceinline__ void split2h(float v0, float v1, uint32_t& hi, uint32_t& lo) {
    __half h0 = __float2half_rn(v0);
    __half h1 = __float2half_rn(v1);
    float r0 = v0 - __half2float(h0);
    float r1 = v1 - __half2float(h1);
    __half2 hh; hh.x = h0; hh.y = h1;
    __half2 ll; ll.x = __float2half_rn(r0); ll.y = __float2half_rn(r1);
    hi = *(uint32_t*)&hh;
    lo = *(uint32_t*)&ll;
}
__device__ __forceinline__ uint32_t pack_h2(float v0, float v1) {
    __half2 h = __floats2half2_rn(v0, v1);
    return *(uint32_t*)&h;
}
__device__ __forceinline__ void split1(float v, unsigned short& h, unsigned short& l) {
    __nv_bfloat16 hb = __float2bfloat16(v);
    float r = v - __bfloat162float(hb);
    __nv_bfloat16 lb = __float2bfloat16(r);
    h = *(unsigned short*)&hb;
    l = *(unsigned short*)&lb;
}
__device__ __forceinline__ void split1h(float v, unsigned short& h, unsigned short& l) {
    __half hb = __float2half_rn(v);
    float r = v - __half2float(hb);
    __half lb = __float2half_rn(r);
    h = *(unsigned short*)&hb;
    l = *(unsigned short*)&lb;
}

// ============================================================================
// K0: pre-split all weights to bf16 hi/lo.
// ============================================================================
__global__ void wsplit_kernel(const float* __restrict__ tw, const float* __restrict__ pw,
                              const float* __restrict__ gw, const float* __restrict__ Ww)
{
    int idx = blockIdx.x * 256 + threadIdx.x;
    if (idx < 49152) {
        int p = idx / 16384, r = idx - p * 16384;
        const float* s = (p == 0) ? tw : (p == 1) ? pw : gw;
        float2 v = *(const float2*)(s + 2 * r);
        uint32_t hi, lo;
        split2(v.x, v.y, hi, lo);
        *(uint32_t*)(gWh + p * 32768 + 2 * r) = hi;
        *(uint32_t*)(gWl + p * 32768 + 2 * r) = lo;
    } else {
        int r = idx - 49152;
        float2 v = *(const float2*)(Ww + 2 * r);
        uint32_t hi, lo;
        split2(v.x, v.y, hi, lo);
        *(uint32_t*)(gWWh + 2 * r) = hi;
        *(uint32_t*)(gWWl + 2 * r) = lo;
    }
}

// ============================================================================
// K0b: transpose+split x -> xT hi/lo [b][n][c].
// ============================================================================
__global__ void xsplit_kernel(const float* __restrict__ x)
{
    __shared__ float xs[64][68];
    const int n0 = blockIdx.x * 64;
    const int c0 = blockIdx.y * 64;
    const int b  = blockIdx.z;
    const int tid = threadIdx.x;
#pragma unroll
    for (int r = 0; r < 4; r++) {
        int fid = tid + (r << 8);
        int cc = fid >> 4, n4 = fid & 15;
        float4 v = *(const float4*)(x + ((size_t)b * CN + c0 + cc) * HWN + n0 + 4 * n4);
        *(float4*)&xs[cc][4 * n4] = v;
    }
    __syncthreads();
#pragma unroll
    for (int r = 0; r < 8; r++) {
        int fid = tid + (r << 8);
        int n = fid >> 5, cp = fid & 31;
        float a  = xs[2 * cp][n];
        float bb = xs[2 * cp + 1][n];
        uint32_t hi, lo;
        split2(a, bb, hi, lo);
        size_t gi = ((size_t)b * HWN + n0 + n) * CN + c0 + 2 * cp;
        *(uint32_t*)(gXh + gi) = hi;
        *(uint32_t*)(gXl + gi) = lo;
    }
}

// ============================================================================
// K1: projections via mma.sync (pre-split operands).
// ============================================================================
__global__ void __launch_bounds__(256) proj_mma_kernel(
    const float* __restrict__ tb, const float* __restrict__ pb, const float* __restrict__ gb)
{
    extern __shared__ char psm[];
    const uint32_t smb = smem_u32(psm);
    unsigned short* sth = (unsigned short*)(psm);            // stage hi [64][130]
    unsigned short* stl = (unsigned short*)(psm + 16640);    // stage lo [64][130]

    const int p  = blockIdx.x;
    const int n0 = blockIdx.y * 64;
    const int b  = blockIdx.z;
    const float* bias = (p == 0) ? tb : (p == 1) ? pb : gb;

    const int tid  = threadIdx.x;
    const int wrp  = tid >> 5;
    const int lane = tid & 31;
    const int qrow = lane >> 2;
    const int qcol = lane & 3;
    const int i0   = 16 * wrp + qrow;

    float acc[8][4];
#pragma unroll
    for (int i = 0; i < 8; i++)
#pragma unroll
        for (int j = 0; j < 4; j++) acc[i][j] = 0.f;

    for (int c0 = 0; c0 < CN; c0 += 64) {
        __syncthreads();
#pragma unroll
        for (int r = 0; r < 4; r++) {
            int fid = tid + (r << 8);
            int pl = fid >> 9, rem = fid & 511;
            int row = rem >> 3, ch = rem & 7;
            const __nv_bfloat16* src = (pl ? gXl : gXh) +
                ((size_t)b * HWN + n0 + row) * CN + c0 + ch * 8;
            cp16(smb + (pl ? PXL : PXH) + row * 144 + ch * 16, src);
        }
#pragma unroll
        for (int r = 0; r < 8; r++) {
            int fid = tid + (r << 8);
            int pl = fid >> 10, rem = fid & 1023;
            int row = rem >> 3, ch = rem & 7;
            const __nv_bfloat16* src = (pl ? gWl : gWh) +
                (size_t)p * 32768 + row * CN + c0 + ch * 8;
            cp16(smb + (pl ? PWL : PWH) + row * 144 + ch * 16, src);
        }
        CP_COMMIT();
        CP_WAIT0();
        __syncthreads();

        uint32_t ah[4][4], al[4][4];
#pragma unroll
        for (int ks = 0; ks < 4; ks++) {
            uint32_t ko = 32 * ks + 4 * qcol;
            ah[ks][0] = lds32(smb + PWH + i0 * 144 + ko);
            ah[ks][1] = lds32(smb + PWH + (i0 + 8) * 144 + ko);
            ah[ks][2] = lds32(smb + PWH + i0 * 144 + ko + 16);
            ah[ks][3] = lds32(smb + PWH + (i0 + 8) * 144 + ko + 16);
            al[ks][0] = lds32(smb + PWL + i0 * 144 + ko);
            al[ks][1] = lds32(smb + PWL + (i0 + 8) * 144 + ko);
            al[ks][2] = lds32(smb + PWL + i0 * 144 + ko + 16);
            al[ks][3] = lds32(smb + PWL + (i0 + 8) * 144 + ko + 16);
        }
#pragma unroll
        for (int ks = 0; ks < 4; ks++) {
#pragma unroll
            for (int nt = 0; nt < 8; nt++) {
                uint32_t ro = (8 * nt + qrow) * 144 + 32 * ks + 4 * qcol;
                uint32_t bh0 = lds32(smb + PXH + ro);
                uint32_t bh1 = lds32(smb + PXH + ro + 16);
                uint32_t bl0 = lds32(smb + PXL + ro);
                uint32_t bl1 = lds32(smb + PXL + ro + 16);
                mma_bf16(acc[nt][0], acc[nt][1], acc[nt][2], acc[nt][3],
                         ah[ks][0], ah[ks][1], ah[ks][2], ah[ks][3], bh0, bh1);
                mma_bf16(acc[nt][0], acc[nt][1], acc[nt][2], acc[nt][3],
                         ah[ks][0], ah[ks][1], ah[ks][2], ah[ks][3], bl0, bl1);
                mma_bf16(acc[nt][0], acc[nt][1], acc[nt][2], acc[nt][3],
                         al[ks][0], al[ks][1], al[ks][2], al[ks][3], bh0, bh1);
            }
        }
    }

    const float bb0 = bias[i0];
    const float bb1 = bias[i0 + 8];
    const float sc  = (p == 1) ? LOG2E : 1.f;

    if (p < 2) {
        // theta/phi -> fp16 hi/lo planes [b][n][k]
        __syncthreads();
#pragma unroll
        for (int nt = 0; nt < 8; nt++) {
            int n = 8 * nt + 2 * qcol;
            float v0 = (acc[nt][0] + bb0) * sc, v1 = (acc[nt][1] + bb0) * sc;
            float v2 = (acc[nt][2] + bb1) * sc, v3 = (acc[nt][3] + bb1) * sc;
            unsigned short h, l;
            split1h(v0, h, l); sth[n * 130 + i0] = h;           stl[n * 130 + i0] = l;
            split1h(v1, h, l); sth[(n + 1) * 130 + i0] = h;     stl[(n + 1) * 130 + i0] = l;
            split1h(v2, h, l); sth[n * 130 + i0 + 8] = h;       stl[n * 130 + i0 + 8] = l;
            split1h(v3, h, l); sth[(n + 1) * 130 + i0 + 8] = h; stl[(n + 1) * 130 + i0 + 8] = l;
        }
        __syncthreads();
        __half* oh = (p == 0) ? gQh : gKh;
        __half* ol = (p == 0) ? gQl : gKl;
#pragma unroll
        for (int r = 0; r < 16; r++) {
            int t = tid + (r << 8);
            int row = t >> 6, w32 = t & 63;
            uint32_t hv = *(uint32_t*)&sth[row * 130 + 2 * w32];
            uint32_t lv = *(uint32_t*)&stl[row * 130 + 2 * w32];
            size_t gb_ = ((size_t)b * HWN + n0 + row) * DN + 2 * w32;
            *(uint32_t*)(oh + gb_) = hv;
            *(uint32_t*)(ol + gb_) = lv;
        }
    } else {
        // g -> fp16 hi/lo planes [b][d][m]
#pragma unroll
        for (int nt = 0; nt < 8; nt++) {
            int n = n0 + 8 * nt + 2 * qcol;
            float v0 = acc[nt][0] + bb0, v1 = acc[nt][1] + bb0;
            float v2 = acc[nt][2] + bb1, v3 = acc[nt][3] + bb1;
            uint32_t h01, l01, h23, l23;
            split2h(v0, v1, h01, l01);
            split2h(v2, v3, h23, l23);
            size_t ba = ((size_t)b * DN + i0) * HWN + n;
            size_t bc = ((size_t)b * DN + i0 + 8) * HWN + n;
            *(uint32_t*)(gVh + ba) = h01;
            *(uint32_t*)(gVl + ba) = l01;
            *(uint32_t*)(gVh + bc) = h23;
            *(uint32_t*)(gVl + bc) = l23;
        }
    }
}

// ============================================================================
// K2: flash attention — fp16 2-term S (q16·kh + q16·kl), fp16 P (running max),
//     fp16 2-term PV. 256 HMMA per warp-tile.
// ============================================================================
__device__ __forceinline__ void load_kv_tile(uint32_t stg, int b, int m0, int tid) {
#pragma unroll
    for (int r = 0; r < 4; r++) {
        int ch = tid + (r << 8);
        int rw = ch >> 4;
        int kc = ch & 15;
        uint32_t dst = stg + rw * K_ROW + (kc << 4);
        size_t gi = (((size_t)b * HWN + m0 + rw) << 7) + (kc << 3);
        cp16(dst + KH_OFF, gKh + gi);
        cp16(dst + KL_OFF, gKl + gi);
    }
#pragma unroll
    for (int r = 0; r < 4; r++) {
        int ch = tid + (r << 8);
        int rw = ch >> 3;
        int mc = ch & 7;
        uint32_t dst = stg + rw * V_ROW + (mc << 4);
        size_t gi = (((size_t)b * DN + rw) << 12) + m0 + (mc << 3);
        cp16(dst + VH_OFF, gVh + gi);
        cp16(dst + VL_OFF, gVl + gi);
    }
}

__global__ void __launch_bounds__(256, 1) attn_mma_kernel()
{
    extern __shared__ char smem[];
    const uint32_t smb = smem_u32(smem);

    const int tid  = threadIdx.x;
    const int lane = tid & 31;
    const int wrp  = tid >> 5;
    const int qrow = lane >> 2;
    const int qcol = lane & 3;
    const int n0   = blockIdx.x * TM;
    const int b    = blockIdx.y;
    const int row0 = 16 * wrp + qrow;

    uint32_t qh[8][4];
    {
        const size_t rbase = ((size_t)b * HWN + n0 + row0) * DN;
#pragma unroll
        for (int ks = 0; ks < 8; ks++) {
            int k0 = 16 * ks + 2 * qcol;
            qh[ks][0] = *(const uint32_t*)(gQh + rbase + k0);
            qh[ks][1] = *(const uint32_t*)(gQh + rbase + 8 * DN + k0);
            qh[ks][2] = *(const uint32_t*)(gQh + rbase + k0 + 8);
            qh[ks][3] = *(const uint32_t*)(gQh + rbase + 8 * DN + k0 + 8);
        }
    }

    float o[16][4];
#pragma unroll
    for (int i = 0; i < 16; i++)
#pragma unroll
        for (int j = 0; j < 4; j++) o[i][j] = 0.f;

    float rs0 = 0.f, rs1 = 0.f;
    float m0 = -INFINITY, m1 = -INFINITY;

    load_kv_tile(smb, b, 0, tid);
    CP_COMMIT();

    for (int t = 0; t < 64; t++) {
        const uint32_t stg = smb + (uint32_t)(t & 1) * STG_SZ;
        __syncthreads();
        if (t + 1 < 64) {
            load_kv_tile(smb + (uint32_t)((t + 1) & 1) * STG_SZ, b, (t + 1) * TN, tid);
            CP_COMMIT();
            CP_WAIT1();
        } else {
            CP_WAIT0();
        }
        __syncthreads();

        // ---- S = q16 K^T (fp16, 2 terms: kh + kl) ----
        float cA[8][4];
#pragma unroll
        for (int nt = 0; nt < 8; nt++) {
            float c0 = 0.f, c1 = 0.f, c2 = 0.f, c3 = 0.f;
            const uint32_t krow = stg + (uint32_t)(8 * nt + qrow) * K_ROW + (uint32_t)(4 * qcol);
#pragma unroll
            for (int ks = 0; ks < 8; ks++) {
                uint32_t bh0 = lds32(krow + KH_OFF + 32 * ks);
                uint32_t bh1 = lds32(krow + KH_OFF + 32 * ks + 16);
                uint32_t bl0 = lds32(krow + KL_OFF + 32 * ks);
                uint32_t bl1 = lds32(krow + KL_OFF + 32 * ks + 16);
                mma_f16(c0, c1, c2, c3, qh[ks][0], qh[ks][1], qh[ks][2], qh[ks][3], bh0, bh1);
                mma_f16(c0, c1, c2, c3, qh[ks][0], qh[ks][1], qh[ks][2], qh[ks][3], bl0, bl1);
            }
            cA[nt][0] = c0; cA[nt][1] = c1; cA[nt][2] = c2; cA[nt][3] = c3;
        }

        // ---- per-tile row max (exp2 domain), running-max rescale ----
        float mx0 = cA[0][0], mx1 = cA[0][2];
#pragma unroll
        for (int nt = 0; nt < 8; nt++) {
            mx0 = fmaxf(mx0, fmaxf(cA[nt][0], cA[nt][1]));
            mx1 = fmaxf(mx1, fmaxf(cA[nt][2], cA[nt][3]));
        }
        mx0 = fmaxf(mx0, __shfl_xor_sync(0xffffffffu, mx0, 1));
        mx0 = fmaxf(mx0, __shfl_xor_sync(0xffffffffu, mx0, 2));
        mx1 = fmaxf(mx1, __shfl_xor_sync(0xffffffffu, mx1, 1));
        mx1 = fmaxf(mx1, __shfl_xor_sync(0xffffffffu, mx1, 2));
        float mn0 = fmaxf(m0, mx0);
        float mn1 = fmaxf(m1, mx1);
        float a0 = ex2(m0 - mn0);
        float a1 = ex2(m1 - mn1);
        m0 = mn0; m1 = mn1;
        rs0 *= a0; rs1 *= a1;
#pragma unroll
        for (int nt = 0; nt < 16; nt++) {
            o[nt][0] *= a0; o[nt][1] *= a0;
            o[nt][2] *= a1; o[nt][3] *= a1;
        }

        // ---- p = 2^(f - m) in fp16 ----
        uint32_t ph[8][2];
#pragma unroll
        for (int nt = 0; nt < 8; nt++) {
            float e0 = ex2(cA[nt][0] - m0), e1 = ex2(cA[nt][1] - m0);
            float e2 = ex2(cA[nt][2] - m1), e3 = ex2(cA[nt][3] - m1);
            rs0 += e0 + e1;
            rs1 += e2 + e3;
            ph[nt][0] = pack_h2(e0, e1);
            ph[nt][1] = pack_h2(e2, e3);
        }

        // ---- O += P V (fp16, 2 terms) ----
#pragma unroll
        for (int ks = 0; ks < 4; ks++) {
            uint32_t ah0 = ph[2 * ks][0], ah1 = ph[2 * ks][1];
            uint32_t ah2 = ph[2 * ks + 1][0], ah3 = ph[2 * ks + 1][1];
            const uint32_t vcol = stg + (uint32_t)(32 * ks + 4 * qcol);
#pragma unroll
            for (int nt = 0; nt < 16; nt++) {
                const uint32_t vrow = vcol + (uint32_t)(8 * nt + qrow) * V_ROW;
                uint32_t bh0 = lds32(vrow + VH_OFF);
                uint32_t bh1 = lds32(vrow + VH_OFF + 16);
                uint32_t bl0 = lds32(vrow + VL_OFF);
                uint32_t bl1 = lds32(vrow + VL_OFF + 16);
                mma_f16(o[nt][0], o[nt][1], o[nt][2], o[nt][3], ah0, ah1, ah2, ah3, bh0, bh1);
                mma_f16(o[nt][0], o[nt][1], o[nt][2], o[nt][3], ah0, ah1, ah2, ah3, bl0, bl1);
            }
        }
    }

    rs0 += __shfl_xor_sync(0xffffffffu, rs0, 1);
    rs0 += __shfl_xor_sync(0xffffffffu, rs0, 2);
    rs1 += __shfl_xor_sync(0xffffffffu, rs1, 1);
    rs1 += __shfl_xor_sync(0xffffffffu, rs1, 2);
    float inv0 = 1.f / rs0;
    float inv1 = 1.f / rs1;

    const size_t y0 = ((size_t)b * HWN + n0 + row0) * DN + 2 * qcol;
    const size_t y1 = y0 + 8 * DN;
#pragma unroll
    for (int nt = 0; nt < 16; nt++) {
        uint32_t h0, l0, h1, l1;
        split2(o[nt][0] * inv0, o[nt][1] * inv0, h0, l0);
        split2(o[nt][2] * inv1, o[nt][3] * inv1, h1, l1);
        *(uint32_t*)(gYh + y0 + 8 * nt) = h0;
        *(uint32_t*)(gYl + y0 + 8 * nt) = l0;
        *(uint32_t*)(gYh + y1 + 8 * nt) = h1;
        *(uint32_t*)(gYl + y1 + 8 * nt) = l1;
    }
}

// ============================================================================
// K3: wy = W*y + b via mma.sync, operands pre-split; fused BN partials.
// ============================================================================
__global__ void __launch_bounds__(256) wgemm_mma_kernel(const float* __restrict__ Wb)
{
    extern __shared__ char wsm[];
    const uint32_t smb = smem_u32(wsm);

    const int c0 = blockIdx.x * 128;
    const int n0 = blockIdx.y * 64;
    const int b  = blockIdx.z;
    const int part = blockIdx.y * 4 + blockIdx.z;

    const int tid  = threadIdx.x;
    const int lane = tid & 31;
    const int wrp  = tid >> 5;
    const int qrow = lane >> 2;
    const int qcol = lane & 3;
    const int c    = c0 + 16 * wrp + qrow;

#pragma unroll
    for (int r = 0; r < 8; r++) {
        int fid = tid + (r << 8);
        int pl = fid >> 10, rem = fid & 1023;
        int row = rem >> 4, ch = rem & 15;
        const __nv_bfloat16* src = (pl ? gYl : gYh) +
            ((size_t)b * HWN + n0 + row) * DN + ch * 8;
        cp16(smb + (pl ? WYL : WYH) + row * 272 + ch * 16, src);
    }
    CP_COMMIT();

    uint32_t ah[8][4], al[8][4];
#pragma unroll
    for (int ks = 0; ks < 8; ks++) {
        int k = 16 * ks + 2 * qcol;
        ah[ks][0] = *(const uint32_t*)(gWWh + (size_t)c * DN + k);
        ah[ks][1] = *(const uint32_t*)(gWWh + (size_t)(c + 8) * DN + k);
        ah[ks][2] = *(const uint32_t*)(gWWh + (size_t)c * DN + k + 8);
        ah[ks][3] = *(const uint32_t*)(gWWh + (size_t)(c + 8) * DN + k + 8);
        al[ks][0] = *(const uint32_t*)(gWWl + (size_t)c * DN + k);
        al[ks][1] = *(const uint32_t*)(gWWl + (size_t)(c + 8) * DN + k);
        al[ks][2] = *(const uint32_t*)(gWWl + (size_t)c * DN + k + 8);
        al[ks][3] = *(const uint32_t*)(gWWl + (size_t)(c + 8) * DN + k + 8);
    }
    CP_WAIT0();
    __syncthreads();

    float acc[8][4];
#pragma unroll
    for (int i = 0; i < 8; i++)
#pragma unroll
        for (int j = 0; j < 4; j++) acc[i][j] = 0.f;

#pragma unroll
    for (int ks = 0; ks < 8; ks++) {
#pragma unroll
        for (int nt = 0; nt < 8; nt++) {
            uint32_t ro = (8 * nt + qrow) * 272 + 32 * ks + 4 * qcol;
            uint32_t bh0 = lds32(smb + WYH + ro);
            uint32_t bh1 = lds32(smb + WYH + ro + 16);
            uint32_t bl0 = lds32(smb + WYL + ro);
            uint32_t bl1 = lds32(smb + WYL + ro + 16);
            mma_bf16(acc[nt][0], acc[nt][1], acc[nt][2], acc[nt][3],
                     ah[ks][0], ah[ks][1], ah[ks][2], ah[ks][3], bh0, bh1);
            mma_bf16(acc[nt][0], acc[nt][1], acc[nt][2], acc[nt][3],
                     ah[ks][0], ah[ks][1], ah[ks][2], ah[ks][3], bl0, bl1);
            mma_bf16(acc[nt][0], acc[nt][1], acc[nt][2], acc[nt][3],
                     al[ks][0], al[ks][1], al[ks][2], al[ks][3], bh0, bh1);
        }
    }

    float bb0 = Wb[c], bb1 = Wb[c + 8];
    float s0 = 0.f, q0 = 0.f, s1 = 0.f, q1 = 0.f;
#pragma unroll
    for (int nt = 0; nt < 8; nt++) {
        int n = n0 + 8 * nt + 2 * qcol;
        float v0 = acc[nt][0] + bb0, v1 = acc[nt][1] + bb0;
        float v2 = acc[nt][2] + bb1, v3 = acc[nt][3] + bb1;
        s0 += v0 + v1; q0 += v0 * v0 + v1 * v1;
        s1 += v2 + v3; q1 += v2 * v2 + v3 * v3;
        *(float2*)(d_WY + ((size_t)b * CN + c) * HWN + n)     = make_float2(v0, v1);
        *(float2*)(d_WY + ((size_t)b * CN + c + 8) * HWN + n) = make_float2(v2, v3);
    }
    s0 += __shfl_xor_sync(0xffffffffu, s0, 1);
    s0 += __shfl_xor_sync(0xffffffffu, s0, 2);
    q0 += __shfl_xor_sync(0xffffffffu, q0, 1);
    q0 += __shfl_xor_sync(0xffffffffu, q0, 2);
    s1 += __shfl_xor_sync(0xffffffffu, s1, 1);
    s1 += __shfl_xor_sync(0xffffffffu, s1, 2);
    q1 += __shfl_xor_sync(0xffffffffu, q1, 1);
    q1 += __shfl_xor_sync(0xffffffffu, q1, 2);
    if (qcol == 0) {
        gPS[c * 256 + part] = s0;
        gPQ[c * 256 + part] = q0;
        gPS[(c + 8) * 256 + part] = s1;
        gPQ[(c + 8) * 256 + part] = q1;
    }
}

// ============================================================================
// K4: BN stats finalize
// ============================================================================
__global__ void bnfinal_kernel()
{
    const int c = blockIdx.x;
    const int tid = threadIdx.x;
    __shared__ float sh[256], sh2[256];
    sh[tid]  = gPS[c * 256 + tid];
    sh2[tid] = gPQ[c * 256 + tid];
    __syncthreads();
    for (int off = 128; off > 0; off >>= 1) {
        if (tid < off) { sh[tid] += sh[tid + off]; sh2[tid] += sh2[tid + off]; }
        __syncthreads();
    }
    if (tid == 0) {
        const float invN = 1.f / (float)(BN * HWN);
        float mean = sh[0] * invN;
        float var  = sh2[0] * invN - mean * mean;
        d_MEAN[c] = mean;
        d_RSTD[c] = rsqrtf(var + 1e-5f);
    }
}

// ============================================================================
// K5: finalize
// ============================================================================
__global__ void finalize_kernel(const float* __restrict__ x,
                                const float* __restrict__ gamma,
                                const float* __restrict__ beta,
                                float* __restrict__ out)
{
    int idx = blockIdx.x * blockDim.x + threadIdx.x;
    int c = (idx >> 10) & 255;
    float4 wv = ((const float4*)d_WY)[idx];
    float4 xv = ((const float4*)x)[idx];
    float g  = gamma[c] * d_RSTD[c];
    float m  = d_MEAN[c];
    float bt = beta[c];
    float4 o;
    o.x = (wv.x - m) * g + bt + xv.x;
    o.y = (wv.y - m) * g + bt + xv.y;
    o.z = (wv.z - m) * g + bt + xv.z;
    o.w = (wv.w - m) * g + bt + xv.w;
    ((float4*)out)[idx] = o;
}

// ============================================================================
extern "C" void kernel_launch(void* const* d_in, const int* in_sizes, int n_in,
                              void* d_out, int out_size)
{
    const float* x     = (const float*)d_in[0];
    const float* tw    = (const float*)d_in[1];
    const float* tb    = (const float*)d_in[2];
    const float* pw    = (const float*)d_in[3];
    const float* pb    = (const float*)d_in[4];
    const float* gw    = (const float*)d_in[5];
    const float* gb    = (const float*)d_in[6];
    const float* Ww    = (const float*)d_in[7];
    const float* Wb    = (const float*)d_in[8];
    const float* gamma = (const float*)d_in[9];
    const float* beta  = (const float*)d_in[10];
    float* out = (float*)d_out;

    cudaFuncSetAttribute(proj_mma_kernel, cudaFuncAttributeMaxDynamicSharedMemorySize, PRJ_SMEM);
    cudaFuncSetAttribute(attn_mma_kernel, cudaFuncAttributeMaxDynamicSharedMemorySize, ATTN_SMEM);
    cudaFuncSetAttribute(wgemm_mma_kernel, cudaFuncAttributeMaxDynamicSharedMemorySize, WG_SMEM);

    wsplit_kernel<<<256, 256>>>(tw, pw, gw, Ww);

    dim3 gx(HWN / 64, CN / 64, BN);
    xsplit_kernel<<<gx, 256>>>(x);

    dim3 g1(3, HWN / 64, BN);
    proj_mma_kernel<<<g1, 256, PRJ_SMEM>>>(tb, pb, gb);

    dim3 g2(HWN / TM, BN);
    attn_mma_kernel<<<g2, 256, ATTN_SMEM>>>();

    dim3 g3(2, HWN / 64, BN);
    wgemm_mma_kernel<<<g3, 256, WG_SMEM>>>(Wb);

    bnfinal_kernel<<<CN, 256>>>();

    finalize_kernel<<<(BN * CN * HWN / 4) / 256, 256>>>(x, gamma, beta, out);
}

// round 14
// speedup vs baseline: 1.4559x; 1.1660x over previous
#include <cuda_runtime.h>
#include <cuda_bf16.h>
#include <cuda_fp16.h>
#include <math.h>
#include <stdint.h>

#define BN   4
#define CN   256
#define HWN  4096
#define DN   128
#define TM   128            // queries per CTA (attention)
#define TN   64             // keys per tile
#define LOG2E 1.4426950408889634f

// attention smem stage layout (bytes)
#define K_ROW   272
#define V_ROW   144
#define KH_OFF  0
#define KL_OFF  (64 * K_ROW)
#define VH_OFF  (2 * 64 * K_ROW)
#define STG_SZ  (2 * 64 * K_ROW + 128 * V_ROW)       // 53248
#define ATTN_SMEM (2 * STG_SZ)                        // 106496

// proj smem (bytes): x planes [64][144B], w planes [128][144B]
#define PXH 0
#define PXL 9216
#define PWH 18432
#define PWL 36864
#define PRJ_SMEM 55296

// wgemm smem: y planes [64][272B]
#define WYH 0
#define WYL 17408
#define WG_SMEM 34816

// -------------------- scratch --------------------
__device__ __align__(128) __nv_bfloat16 gXh[BN * HWN * CN];  // x^T hi [b][n][c]
__device__ __align__(128) __nv_bfloat16 gXl[BN * HWN * CN];
__device__ __align__(128) __nv_bfloat16 gWh[3 * DN * CN];    // proj weights hi [p][i][c]
__device__ __align__(128) __nv_bfloat16 gWl[3 * DN * CN];
__device__ __align__(128) __nv_bfloat16 gWWh[CN * DN];       // W hi [c][i]
__device__ __align__(128) __nv_bfloat16 gWWl[CN * DN];
__device__ __align__(128) __half gQh[BN * HWN * DN];         // theta fp16 [b][n][k]
__device__ __align__(128) __half gKh[BN * HWN * DN];         // phi(scaled) hi fp16 [b][m][k]
__device__ __align__(128) __half gKl[BN * HWN * DN];         // phi lo fp16
__device__ __align__(128) __half gVh[BN * DN * HWN];         // g fp16 [b][d][m]
__device__ __align__(128) __nv_bfloat16 gYh[BN * HWN * DN];  // attn out hi [b][n][i]
__device__ __align__(128) __nv_bfloat16 gYl[BN * HWN * DN];
__device__ __align__(128) float d_WY[BN * CN * HWN];         // [b][c][n]
__device__ float gPS[CN * 256];
__device__ float gPQ[CN * 256];
__device__ float d_MEAN[CN];
__device__ float d_RSTD[CN];

// ======================= helpers =======================
__device__ __forceinline__ uint32_t smem_u32(const void* p) {
    uint32_t a;
    asm("{ .reg .u64 t; cvta.to.shared.u64 t, %1; cvt.u32.u64 %0, t; }" : "=r"(a) : "l"(p));
    return a;
}
__device__ __forceinline__ void cp16(uint32_t dst, const void* src) {
    asm volatile("cp.async.cg.shared.global [%0], [%1], 16;" :: "r"(dst), "l"(src));
}
#define CP_COMMIT() asm volatile("cp.async.commit_group;" ::: "memory")
#define CP_WAIT0()  asm volatile("cp.async.wait_group 0;" ::: "memory")
#define CP_WAIT1()  asm volatile("cp.async.wait_group 1;" ::: "memory")

__device__ __forceinline__ void mma_bf16(float& c0, float& c1, float& c2, float& c3,
                                         uint32_t a0, uint32_t a1, uint32_t a2, uint32_t a3,
                                         uint32_t b0, uint32_t b1) {
    asm volatile("mma.sync.aligned.m16n8k16.row.col.f32.bf16.bf16.f32 "
                 "{%0,%1,%2,%3}, {%4,%5,%6,%7}, {%8,%9}, {%0,%1,%2,%3};"
                 : "+f"(c0), "+f"(c1), "+f"(c2), "+f"(c3)
                 : "r"(a0), "r"(a1), "r"(a2), "r"(a3), "r"(b0), "r"(b1));
}
__device__ __forceinline__ void mma_f16(float& c0, float& c1, float& c2, float& c3,
                                        uint32_t a0, uint32_t a1, uint32_t a2, uint32_t a3,
                                        uint32_t b0, uint32_t b1) {
    asm volatile("mma.sync.aligned.m16n8k16.row.col.f32.f16.f16.f32 "
                 "{%0,%1,%2,%3}, {%4,%5,%6,%7}, {%8,%9}, {%0,%1,%2,%3};"
                 : "+f"(c0), "+f"(c1), "+f"(c2), "+f"(c3)
                 : "r"(a0), "r"(a1), "r"(a2), "r"(a3), "r"(b0), "r"(b1));
}
__device__ __forceinline__ void mma_f16acc(uint32_t& d0, uint32_t& d1,
                                           uint32_t a0, uint32_t a1, uint32_t a2, uint32_t a3,
                                           uint32_t b0, uint32_t b1) {
    asm volatile("mma.sync.aligned.m16n8k16.row.col.f16.f16.f16.f16 "
                 "{%0,%1}, {%2,%3,%4,%5}, {%6,%7}, {%0,%1};"
                 : "+r"(d0), "+r"(d1)
                 : "r"(a0), "r"(a1), "r"(a2), "r"(a3), "r"(b0), "r"(b1));
}
__device__ __forceinline__ uint32_t lds32(uint32_t addr) {
    uint32_t v;
    asm volatile("ld.shared.b32 %0, [%1];" : "=r"(v) : "r"(addr));
    return v;
}
__device__ __forceinline__ float ex2(float x) {
    float y;
    asm("ex2.approx.ftz.f32 %0, %1;" : "=f"(y) : "f"(x));
    return y;
}
__device__ __forceinline__ void split2(float v0, float v1, uint32_t& hi, uint32_t& lo) {
    __nv_bfloat16 h0 = __float2bfloat16(v0);
    __nv_bfloat16 h1 = __float2bfloat16(v1);
    float r0 = v0 - __bfloat162float(h0);
    float r1 = v1 - __bfloat162float(h1);
    __nv_bfloat162 hh; hh.x = h0; hh.y = h1;
    __nv_bfloat162 ll; ll.x = __float2bfloat16(r0); ll.y = __float2bfloat16(r1);
    hi = *(uint32_t*)&hh;
    lo = *(uint32_t*)&ll;
}
__device__ __forceinline__ uint32_t pack_h2(float v0, float v1) {
    __half2 h = __floats2half2_rn(v0, v1);
    return *(uint32_t*)&h;
}
__device__ __forceinline__ void split1(float v, unsigned short& h, unsigned short& l) {
    __nv_bfloat16 hb = __float2bfloat16(v);
    float r = v - __bfloat162float(hb);
    __nv_bfloat16 lb = __float2bfloat16(r);
    h = *(unsigned short*)&hb;
    l = *(unsigned short*)&lb;
}
__device__ __forceinline__ void split1h(float v, unsigned short& h, unsigned short& l) {
    __half hb = __float2half_rn(v);
    float r = v - __half2float(hb);
    __half lb = __float2half_rn(r);
    h = *(unsigned short*)&hb;
    l = *(unsigned short*)&lb;
}

// ============================================================================
// K0: pre-split all weights to bf16 hi/lo.
// ============================================================================
__global__ void wsplit_kernel(const float* __restrict__ tw, const float* __restrict__ pw,
                              const float* __restrict__ gw, const float* __restrict__ Ww)
{
    int idx = blockIdx.x * 256 + threadIdx.x;
    if (idx < 49152) {
        int p = idx / 16384, r = idx - p * 16384;
        const float* s = (p == 0) ? tw : (p == 1) ? pw : gw;
        float2 v = *(const float2*)(s + 2 * r);
        uint32_t hi, lo;
        split2(v.x, v.y, hi, lo);
        *(uint32_t*)(gWh + p * 32768 + 2 * r) = hi;
        *(uint32_t*)(gWl + p * 32768 + 2 * r) = lo;
    } else {
        int r = idx - 49152;
        float2 v = *(const float2*)(Ww + 2 * r);
        uint32_t hi, lo;
        split2(v.x, v.y, hi, lo);
        *(uint32_t*)(gWWh + 2 * r) = hi;
        *(uint32_t*)(gWWl + 2 * r) = lo;
    }
}

// ============================================================================
// K0b: transpose+split x -> xT hi/lo [b][n][c].
// ============================================================================
__global__ void xsplit_kernel(const float* __restrict__ x)
{
    __shared__ float xs[64][68];
    const int n0 = blockIdx.x * 64;
    const int c0 = blockIdx.y * 64;
    const int b  = blockIdx.z;
    const int tid = threadIdx.x;
#pragma unroll
    for (int r = 0; r < 4; r++) {
        int fid = tid + (r << 8);
        int cc = fid >> 4, n4 = fid & 15;
        float4 v = *(const float4*)(x + ((size_t)b * CN + c0 + cc) * HWN + n0 + 4 * n4);
        *(float4*)&xs[cc][4 * n4] = v;
    }
    __syncthreads();
#pragma unroll
    for (int r = 0; r < 8; r++) {
        int fid = tid + (r << 8);
        int n = fid >> 5, cp = fid & 31;
        float a  = xs[2 * cp][n];
        float bb = xs[2 * cp + 1][n];
        uint32_t hi, lo;
        split2(a, bb, hi, lo);
        size_t gi = ((size_t)b * HWN + n0 + n) * CN + c0 + 2 * cp;
        *(uint32_t*)(gXh + gi) = hi;
        *(uint32_t*)(gXl + gi) = lo;
    }
}

// ============================================================================
// K1: projections via mma.sync (pre-split operands).
// ============================================================================
__global__ void __launch_bounds__(256) proj_mma_kernel(
    const float* __restrict__ tb, const float* __restrict__ pb, const float* __restrict__ gb)
{
    extern __shared__ char psm[];
    const uint32_t smb = smem_u32(psm);
    unsigned short* sth = (unsigned short*)(psm);            // stage hi [64][130]
    unsigned short* stl = (unsigned short*)(psm + 16640);    // stage lo [64][130]

    const int p  = blockIdx.x;
    const int n0 = blockIdx.y * 64;
    const int b  = blockIdx.z;
    const float* bias = (p == 0) ? tb : (p == 1) ? pb : gb;

    const int tid  = threadIdx.x;
    const int wrp  = tid >> 5;
    const int lane = tid & 31;
    const int qrow = lane >> 2;
    const int qcol = lane & 3;
    const int i0   = 16 * wrp + qrow;

    float acc[8][4];
#pragma unroll
    for (int i = 0; i < 8; i++)
#pragma unroll
        for (int j = 0; j < 4; j++) acc[i][j] = 0.f;

    for (int c0 = 0; c0 < CN; c0 += 64) {
        __syncthreads();
#pragma unroll
        for (int r = 0; r < 4; r++) {
            int fid = tid + (r << 8);
            int pl = fid >> 9, rem = fid & 511;
            int row = rem >> 3, ch = rem & 7;
            const __nv_bfloat16* src = (pl ? gXl : gXh) +
                ((size_t)b * HWN + n0 + row) * CN + c0 + ch * 8;
            cp16(smb + (pl ? PXL : PXH) + row * 144 + ch * 16, src);
        }
#pragma unroll
        for (int r = 0; r < 8; r++) {
            int fid = tid + (r << 8);
            int pl = fid >> 10, rem = fid & 1023;
            int row = rem >> 3, ch = rem & 7;
            const __nv_bfloat16* src = (pl ? gWl : gWh) +
                (size_t)p * 32768 + row * CN + c0 + ch * 8;
            cp16(smb + (pl ? PWL : PWH) + row * 144 + ch * 16, src);
        }
        CP_COMMIT();
        CP_WAIT0();
        __syncthreads();

        uint32_t ah[4][4], al[4][4];
#pragma unroll
        for (int ks = 0; ks < 4; ks++) {
            uint32_t ko = 32 * ks + 4 * qcol;
            ah[ks][0] = lds32(smb + PWH + i0 * 144 + ko);
            ah[ks][1] = lds32(smb + PWH + (i0 + 8) * 144 + ko);
            ah[ks][2] = lds32(smb + PWH + i0 * 144 + ko + 16);
            ah[ks][3] = lds32(smb + PWH + (i0 + 8) * 144 + ko + 16);
            al[ks][0] = lds32(smb + PWL + i0 * 144 + ko);
            al[ks][1] = lds32(smb + PWL + (i0 + 8) * 144 + ko);
            al[ks][2] = lds32(smb + PWL + i0 * 144 + ko + 16);
            al[ks][3] = lds32(smb + PWL + (i0 + 8) * 144 + ko + 16);
        }
#pragma unroll
        for (int ks = 0; ks < 4; ks++) {
#pragma unroll
            for (int nt = 0; nt < 8; nt++) {
                uint32_t ro = (8 * nt + qrow) * 144 + 32 * ks + 4 * qcol;
                uint32_t bh0 = lds32(smb + PXH + ro);
                uint32_t bh1 = lds32(smb + PXH + ro + 16);
                uint32_t bl0 = lds32(smb + PXL + ro);
                uint32_t bl1 = lds32(smb + PXL + ro + 16);
                mma_bf16(acc[nt][0], acc[nt][1], acc[nt][2], acc[nt][3],
                         ah[ks][0], ah[ks][1], ah[ks][2], ah[ks][3], bh0, bh1);
                mma_bf16(acc[nt][0], acc[nt][1], acc[nt][2], acc[nt][3],
                         ah[ks][0], ah[ks][1], ah[ks][2], ah[ks][3], bl0, bl1);
                mma_bf16(acc[nt][0], acc[nt][1], acc[nt][2], acc[nt][3],
                         al[ks][0], al[ks][1], al[ks][2], al[ks][3], bh0, bh1);
            }
        }
    }

    const float bb0 = bias[i0];
    const float bb1 = bias[i0 + 8];
    const float sc  = (p == 1) ? LOG2E : 1.f;

    if (p < 2) {
        // theta/phi -> fp16 hi/lo planes [b][n][k] (theta lo unused)
        __syncthreads();
#pragma unroll
        for (int nt = 0; nt < 8; nt++) {
            int n = 8 * nt + 2 * qcol;
            float v0 = (acc[nt][0] + bb0) * sc, v1 = (acc[nt][1] + bb0) * sc;
            float v2 = (acc[nt][2] + bb1) * sc, v3 = (acc[nt][3] + bb1) * sc;
            unsigned short h, l;
            split1h(v0, h, l); sth[n * 130 + i0] = h;           stl[n * 130 + i0] = l;
            split1h(v1, h, l); sth[(n + 1) * 130 + i0] = h;     stl[(n + 1) * 130 + i0] = l;
            split1h(v2, h, l); sth[n * 130 + i0 + 8] = h;       stl[n * 130 + i0 + 8] = l;
            split1h(v3, h, l); sth[(n + 1) * 130 + i0 + 8] = h; stl[(n + 1) * 130 + i0 + 8] = l;
        }
        __syncthreads();
        if (p == 0) {
#pragma unroll
            for (int r = 0; r < 16; r++) {
                int t = tid + (r << 8);
                int row = t >> 6, w32 = t & 63;
                uint32_t hv = *(uint32_t*)&sth[row * 130 + 2 * w32];
                size_t gb_ = ((size_t)b * HWN + n0 + row) * DN + 2 * w32;
                *(uint32_t*)(gQh + gb_) = hv;
            }
        } else {
#pragma unroll
            for (int r = 0; r < 16; r++) {
                int t = tid + (r << 8);
                int row = t >> 6, w32 = t & 63;
                uint32_t hv = *(uint32_t*)&sth[row * 130 + 2 * w32];
                uint32_t lv = *(uint32_t*)&stl[row * 130 + 2 * w32];
                size_t gb_ = ((size_t)b * HWN + n0 + row) * DN + 2 * w32;
                *(uint32_t*)(gKh + gb_) = hv;
                *(uint32_t*)(gKl + gb_) = lv;
            }
        }
    } else {
        // g -> single fp16 plane [b][d][m]
#pragma unroll
        for (int nt = 0; nt < 8; nt++) {
            int n = n0 + 8 * nt + 2 * qcol;
            float v0 = acc[nt][0] + bb0, v1 = acc[nt][1] + bb0;
            float v2 = acc[nt][2] + bb1, v3 = acc[nt][3] + bb1;
            size_t ba = ((size_t)b * DN + i0) * HWN + n;
            size_t bc = ((size_t)b * DN + i0 + 8) * HWN + n;
            *(uint32_t*)(gVh + ba) = pack_h2(v0, v1);
            *(uint32_t*)(gVh + bc) = pack_h2(v2, v3);
        }
    }
}

// ============================================================================
// K2: flash attention — fp16 2-term S, fp16 P (running max), single-term fp16
//     PV with fp16 accumulators. 192 HMMA per warp-tile.
// ============================================================================
__device__ __forceinline__ void load_kv_tile(uint32_t stg, int b, int m0, int tid) {
#pragma unroll
    for (int r = 0; r < 4; r++) {
        int ch = tid + (r << 8);
        int rw = ch >> 4;
        int kc = ch & 15;
        uint32_t dst = stg + rw * K_ROW + (kc << 4);
        size_t gi = (((size_t)b * HWN + m0 + rw) << 7) + (kc << 3);
        cp16(dst + KH_OFF, gKh + gi);
        cp16(dst + KL_OFF, gKl + gi);
    }
#pragma unroll
    for (int r = 0; r < 4; r++) {
        int ch = tid + (r << 8);
        int rw = ch >> 3;
        int mc = ch & 7;
        uint32_t dst = stg + rw * V_ROW + (mc << 4);
        size_t gi = (((size_t)b * DN + rw) << 12) + m0 + (mc << 3);
        cp16(dst + VH_OFF, gVh + gi);
    }
}

__global__ void __launch_bounds__(256, 1) attn_mma_kernel()
{
    extern __shared__ char smem[];
    const uint32_t smb = smem_u32(smem);

    const int tid  = threadIdx.x;
    const int lane = tid & 31;
    const int wrp  = tid >> 5;
    const int qrow = lane >> 2;
    const int qcol = lane & 3;
    const int n0   = blockIdx.x * TM;
    const int b    = blockIdx.y;
    const int row0 = 16 * wrp + qrow;

    uint32_t qh[8][4];
    {
        const size_t rbase = ((size_t)b * HWN + n0 + row0) * DN;
#pragma unroll
        for (int ks = 0; ks < 8; ks++) {
            int k0 = 16 * ks + 2 * qcol;
            qh[ks][0] = *(const uint32_t*)(gQh + rbase + k0);
            qh[ks][1] = *(const uint32_t*)(gQh + rbase + 8 * DN + k0);
            qh[ks][2] = *(const uint32_t*)(gQh + rbase + k0 + 8);
            qh[ks][3] = *(const uint32_t*)(gQh + rbase + 8 * DN + k0 + 8);
        }
    }

    float o[16][4];
#pragma unroll
    for (int i = 0; i < 16; i++)
#pragma unroll
        for (int j = 0; j < 4; j++) o[i][j] = 0.f;

    float rs0 = 0.f, rs1 = 0.f;
    float m0 = -INFINITY, m1 = -INFINITY;

    load_kv_tile(smb, b, 0, tid);
    CP_COMMIT();

    for (int t = 0; t < 64; t++) {
        const uint32_t stg = smb + (uint32_t)(t & 1) * STG_SZ;
        __syncthreads();
        if (t + 1 < 64) {
            load_kv_tile(smb + (uint32_t)((t + 1) & 1) * STG_SZ, b, (t + 1) * TN, tid);
            CP_COMMIT();
            CP_WAIT1();
        } else {
            CP_WAIT0();
        }
        __syncthreads();

        // ---- S = q16 K^T (fp16, 2 terms: kh + kl) ----
        float cA[8][4];
#pragma unroll
        for (int nt = 0; nt < 8; nt++) {
            float c0 = 0.f, c1 = 0.f, c2 = 0.f, c3 = 0.f;
            const uint32_t krow = stg + (uint32_t)(8 * nt + qrow) * K_ROW + (uint32_t)(4 * qcol);
#pragma unroll
            for (int ks = 0; ks < 8; ks++) {
                uint32_t bh0 = lds32(krow + KH_OFF + 32 * ks);
                uint32_t bh1 = lds32(krow + KH_OFF + 32 * ks + 16);
                uint32_t bl0 = lds32(krow + KL_OFF + 32 * ks);
                uint32_t bl1 = lds32(krow + KL_OFF + 32 * ks + 16);
                mma_f16(c0, c1, c2, c3, qh[ks][0], qh[ks][1], qh[ks][2], qh[ks][3], bh0, bh1);
                mma_f16(c0, c1, c2, c3, qh[ks][0], qh[ks][1], qh[ks][2], qh[ks][3], bl0, bl1);
            }
            cA[nt][0] = c0; cA[nt][1] = c1; cA[nt][2] = c2; cA[nt][3] = c3;
        }

        // ---- per-tile row max (exp2 domain), running-max rescale ----
        float mx0 = cA[0][0], mx1 = cA[0][2];
#pragma unroll
        for (int nt = 0; nt < 8; nt++) {
            mx0 = fmaxf(mx0, fmaxf(cA[nt][0], cA[nt][1]));
            mx1 = fmaxf(mx1, fmaxf(cA[nt][2], cA[nt][3]));
        }
        mx0 = fmaxf(mx0, __shfl_xor_sync(0xffffffffu, mx0, 1));
        mx0 = fmaxf(mx0, __shfl_xor_sync(0xffffffffu, mx0, 2));
        mx1 = fmaxf(mx1, __shfl_xor_sync(0xffffffffu, mx1, 1));
        mx1 = fmaxf(mx1, __shfl_xor_sync(0xffffffffu, mx1, 2));
        float mn0 = fmaxf(m0, mx0);
        float mn1 = fmaxf(m1, mx1);
        float a0 = ex2(m0 - mn0);
        float a1 = ex2(m1 - mn1);
        m0 = mn0; m1 = mn1;
        rs0 *= a0; rs1 *= a1;
#pragma unroll
        for (int nt = 0; nt < 16; nt++) {
            o[nt][0] *= a0; o[nt][1] *= a0;
            o[nt][2] *= a1; o[nt][3] *= a1;
        }

        // ---- p = 2^(f - m) in fp16 ----
        uint32_t ph[8][2];
#pragma unroll
        for (int nt = 0; nt < 8; nt++) {
            float e0 = ex2(cA[nt][0] - m0), e1 = ex2(cA[nt][1] - m0);
            float e2 = ex2(cA[nt][2] - m1), e3 = ex2(cA[nt][3] - m1);
            rs0 += e0 + e1;
            rs1 += e2 + e3;
            ph[nt][0] = pack_h2(e0, e1);
            ph[nt][1] = pack_h2(e2, e3);
        }

        // ---- O_tile = P V in fp16 accumulators, then add to fp32 O ----
#pragma unroll
        for (int nt = 0; nt < 16; nt++) {
            uint32_t d0 = 0, d1 = 0;
            const uint32_t vrow = stg + VH_OFF + (uint32_t)(8 * nt + qrow) * V_ROW
                                + (uint32_t)(4 * qcol);
#pragma unroll
            for (int ks = 0; ks < 4; ks++) {
                uint32_t bh0 = lds32(vrow + 32 * ks);
                uint32_t bh1 = lds32(vrow + 32 * ks + 16);
                mma_f16acc(d0, d1,
                           ph[2 * ks][0], ph[2 * ks][1],
                           ph[2 * ks + 1][0], ph[2 * ks + 1][1],
                           bh0, bh1);
            }
            float2 f0 = __half22float2(*(__half2*)&d0);
            float2 f1 = __half22float2(*(__half2*)&d1);
            o[nt][0] += f0.x; o[nt][1] += f0.y;
            o[nt][2] += f1.x; o[nt][3] += f1.y;
        }
    }

    rs0 += __shfl_xor_sync(0xffffffffu, rs0, 1);
    rs0 += __shfl_xor_sync(0xffffffffu, rs0, 2);
    rs1 += __shfl_xor_sync(0xffffffffu, rs1, 1);
    rs1 += __shfl_xor_sync(0xffffffffu, rs1, 2);
    float inv0 = 1.f / rs0;
    float inv1 = 1.f / rs1;

    const size_t y0 = ((size_t)b * HWN + n0 + row0) * DN + 2 * qcol;
    const size_t y1 = y0 + 8 * DN;
#pragma unroll
    for (int nt = 0; nt < 16; nt++) {
        uint32_t h0, l0, h1, l1;
        split2(o[nt][0] * inv0, o[nt][1] * inv0, h0, l0);
        split2(o[nt][2] * inv1, o[nt][3] * inv1, h1, l1);
        *(uint32_t*)(gYh + y0 + 8 * nt) = h0;
        *(uint32_t*)(gYl + y0 + 8 * nt) = l0;
        *(uint32_t*)(gYh + y1 + 8 * nt) = h1;
        *(uint32_t*)(gYl + y1 + 8 * nt) = l1;
    }
}

// ============================================================================
// K3: wy = W*y + b via mma.sync, operands pre-split; fused BN partials.
// ============================================================================
__global__ void __launch_bounds__(256) wgemm_mma_kernel(const float* __restrict__ Wb)
{
    extern __shared__ char wsm[];
    const uint32_t smb = smem_u32(wsm);

    const int c0 = blockIdx.x * 128;
    const int n0 = blockIdx.y * 64;
    const int b  = blockIdx.z;
    const int part = blockIdx.y * 4 + blockIdx.z;

    const int tid  = threadIdx.x;
    const int lane = tid & 31;
    const int wrp  = tid >> 5;
    const int qrow = lane >> 2;
    const int qcol = lane & 3;
    const int c    = c0 + 16 * wrp + qrow;

#pragma unroll
    for (int r = 0; r < 8; r++) {
        int fid = tid + (r << 8);
        int pl = fid >> 10, rem = fid & 1023;
        int row = rem >> 4, ch = rem & 15;
        const __nv_bfloat16* src = (pl ? gYl : gYh) +
            ((size_t)b * HWN + n0 + row) * DN + ch * 8;
        cp16(smb + (pl ? WYL : WYH) + row * 272 + ch * 16, src);
    }
    CP_COMMIT();

    uint32_t ah[8][4], al[8][4];
#pragma unroll
    for (int ks = 0; ks < 8; ks++) {
        int k = 16 * ks + 2 * qcol;
        ah[ks][0] = *(const uint32_t*)(gWWh + (size_t)c * DN + k);
        ah[ks][1] = *(const uint32_t*)(gWWh + (size_t)(c + 8) * DN + k);
        ah[ks][2] = *(const uint32_t*)(gWWh + (size_t)c * DN + k + 8);
        ah[ks][3] = *(const uint32_t*)(gWWh + (size_t)(c + 8) * DN + k + 8);
        al[ks][0] = *(const uint32_t*)(gWWl + (size_t)c * DN + k);
        al[ks][1] = *(const uint32_t*)(gWWl + (size_t)(c + 8) * DN + k);
        al[ks][2] = *(const uint32_t*)(gWWl + (size_t)c * DN + k + 8);
        al[ks][3] = *(const uint32_t*)(gWWl + (size_t)(c + 8) * DN + k + 8);
    }
    CP_WAIT0();
    __syncthreads();

    float acc[8][4];
#pragma unroll
    for (int i = 0; i < 8; i++)
#pragma unroll
        for (int j = 0; j < 4; j++) acc[i][j] = 0.f;

#pragma unroll
    for (int ks = 0; ks < 8; ks++) {
#pragma unroll
        for (int nt = 0; nt < 8; nt++) {
            uint32_t ro = (8 * nt + qrow) * 272 + 32 * ks + 4 * qcol;
            uint32_t bh0 = lds32(smb + WYH + ro);
            uint32_t bh1 = lds32(smb + WYH + ro + 16);
            uint32_t bl0 = lds32(smb + WYL + ro);
            uint32_t bl1 = lds32(smb + WYL + ro + 16);
            mma_bf16(acc[nt][0], acc[nt][1], acc[nt][2], acc[nt][3],
                     ah[ks][0], ah[ks][1], ah[ks][2], ah[ks][3], bh0, bh1);
            mma_bf16(acc[nt][0], acc[nt][1], acc[nt][2], acc[nt][3],
                     ah[ks][0], ah[ks][1], ah[ks][2], ah[ks][3], bl0, bl1);
            mma_bf16(acc[nt][0], acc[nt][1], acc[nt][2], acc[nt][3],
                     al[ks][0], al[ks][1], al[ks][2], al[ks][3], bh0, bh1);
        }
    }

    float bb0 = Wb[c], bb1 = Wb[c + 8];
    float s0 = 0.f, q0 = 0.f, s1 = 0.f, q1 = 0.f;
#pragma unroll
    for (int nt = 0; nt < 8; nt++) {
        int n = n0 + 8 * nt + 2 * qcol;
        float v0 = acc[nt][0] + bb0, v1 = acc[nt][1] + bb0;
        float v2 = acc[nt][2] + bb1, v3 = acc[nt][3] + bb1;
        s0 += v0 + v1; q0 += v0 * v0 + v1 * v1;
        s1 += v2 + v3; q1 += v2 * v2 + v3 * v3;
        *(float2*)(d_WY + ((size_t)b * CN + c) * HWN + n)     = make_float2(v0, v1);
        *(float2*)(d_WY + ((size_t)b * CN + c + 8) * HWN + n) = make_float2(v2, v3);
    }
    s0 += __shfl_xor_sync(0xffffffffu, s0, 1);
    s0 += __shfl_xor_sync(0xffffffffu, s0, 2);
    q0 += __shfl_xor_sync(0xffffffffu, q0, 1);
    q0 += __shfl_xor_sync(0xffffffffu, q0, 2);
    s1 += __shfl_xor_sync(0xffffffffu, s1, 1);
    s1 += __shfl_xor_sync(0xffffffffu, s1, 2);
    q1 += __shfl_xor_sync(0xffffffffu, q1, 1);
    q1 += __shfl_xor_sync(0xffffffffu, q1, 2);
    if (qcol == 0) {
        gPS[c * 256 + part] = s0;
        gPQ[c * 256 + part] = q0;
        gPS[(c + 8) * 256 + part] = s1;
        gPQ[(c + 8) * 256 + part] = q1;
    }
}

// ============================================================================
// K4: BN stats finalize
// ============================================================================
__global__ void bnfinal_kernel()
{
    const int c = blockIdx.x;
    const int tid = threadIdx.x;
    __shared__ float sh[256], sh2[256];
    sh[tid]  = gPS[c * 256 + tid];
    sh2[tid] = gPQ[c * 256 + tid];
    __syncthreads();
    for (int off = 128; off > 0; off >>= 1) {
        if (tid < off) { sh[tid] += sh[tid + off]; sh2[tid] += sh2[tid + off]; }
        __syncthreads();
    }
    if (tid == 0) {
        const float invN = 1.f / (float)(BN * HWN);
        float mean = sh[0] * invN;
        float var  = sh2[0] * invN - mean * mean;
        d_MEAN[c] = mean;
        d_RSTD[c] = rsqrtf(var + 1e-5f);
    }
}

// ============================================================================
// K5: finalize
// ============================================================================
__global__ void finalize_kernel(const float* __restrict__ x,
                                const float* __restrict__ gamma,
                                const float* __restrict__ beta,
                                float* __restrict__ out)
{
    int idx = blockIdx.x * blockDim.x + threadIdx.x;
    int c = (idx >> 10) & 255;
    float4 wv = ((const float4*)d_WY)[idx];
    float4 xv = ((const float4*)x)[idx];
    float g  = gamma[c] * d_RSTD[c];
    float m  = d_MEAN[c];
    float bt = beta[c];
    float4 o;
    o.x = (wv.x - m) * g + bt + xv.x;
    o.y = (wv.y - m) * g + bt + xv.y;
    o.z = (wv.z - m) * g + bt + xv.z;
    o.w = (wv.w - m) * g + bt + xv.w;
    ((float4*)out)[idx] = o;
}

// ============================================================================
extern "C" void kernel_launch(void* const* d_in, const int* in_sizes, int n_in,
                              void* d_out, int out_size)
{
    const float* x     = (const float*)d_in[0];
    const float* tw    = (const float*)d_in[1];
    const float* tb    = (const float*)d_in[2];
    const float* pw    = (const float*)d_in[3];
    const float* pb    = (const float*)d_in[4];
    const float* gw    = (const float*)d_in[5];
    const float* gb    = (const float*)d_in[6];
    const float* Ww    = (const float*)d_in[7];
    const float* Wb    = (const float*)d_in[8];
    const float* gamma = (const float*)d_in[9];
    const float* beta  = (const float*)d_in[10];
    float* out = (float*)d_out;

    cudaFuncSetAttribute(proj_mma_kernel, cudaFuncAttributeMaxDynamicSharedMemorySize, PRJ_SMEM);
    cudaFuncSetAttribute(attn_mma_kernel, cudaFuncAttributeMaxDynamicSharedMemorySize, ATTN_SMEM);
    cudaFuncSetAttribute(wgemm_mma_kernel, cudaFuncAttributeMaxDynamicSharedMemorySize, WG_SMEM);

    wsplit_kernel<<<256, 256>>>(tw, pw, gw, Ww);

    dim3 gx(HWN / 64, CN / 64, BN);
    xsplit_kernel<<<gx, 256>>>(x);

    dim3 g1(3, HWN / 64, BN);
    proj_mma_kernel<<<g1, 256, PRJ_SMEM>>>(tb, pb, gb);

    dim3 g2(HWN / TM, BN);
    attn_mma_kernel<<<g2, 256, ATTN_SMEM>>>();

    dim3 g3(2, HWN / 64, BN);
    wgemm_mma_kernel<<<g3, 256, WG_SMEM>>>(Wb);

    bnfinal_kernel<<<CN, 256>>>();

    finalize_kernel<<<(BN * CN * HWN / 4) / 256, 256>>>(x, gamma, beta, out);
}

// round 15
// speedup vs baseline: 1.8275x; 1.2553x over previous
#include <cuda_runtime.h>
#include <cuda_bf16.h>
#include <cuda_fp16.h>
#include <math.h>
#include <stdint.h>

#define BN   4
#define CN   256
#define HWN  4096
#define DN   128
#define TM   128            // queries per CTA (attention)
#define TN   64             // keys per tile
#define LOG2E 1.4426950408889634f

// attention smem stage layout (bytes): K fp16 [64][272B], V fp16 [128][144B]
#define K_ROW   272
#define V_ROW   144
#define KH_OFF  0
#define VH_OFF  (64 * K_ROW)                          // 17408
#define STG_SZ  (64 * K_ROW + 128 * V_ROW)            // 35840
#define ATTN_SMEM (2 * STG_SZ)                        // 71680

// proj smem (bytes): x planes [64][144B], w planes [128][144B]
#define PXH 0
#define PXL 9216
#define PWH 18432
#define PWL 36864
#define PRJ_SMEM 55296

// wgemm smem: y planes [64][272B]
#define WYH 0
#define WYL 17408
#define WG_SMEM 34816

// -------------------- scratch --------------------
__device__ __align__(128) __nv_bfloat16 gXh[BN * HWN * CN];  // x^T hi [b][n][c]
__device__ __align__(128) __nv_bfloat16 gXl[BN * HWN * CN];
__device__ __align__(128) __nv_bfloat16 gWh[3 * DN * CN];    // proj weights hi [p][i][c]
__device__ __align__(128) __nv_bfloat16 gWl[3 * DN * CN];
__device__ __align__(128) __nv_bfloat16 gWWh[CN * DN];       // W hi [c][i]
__device__ __align__(128) __nv_bfloat16 gWWl[CN * DN];
__device__ __align__(128) __half gQh[BN * HWN * DN];         // theta fp16 [b][n][k]
__device__ __align__(128) __half gKh[BN * HWN * DN];         // phi(scaled) fp16 [b][m][k]
__device__ __align__(128) __half gVh[BN * DN * HWN];         // g fp16 [b][d][m]
__device__ __align__(128) __nv_bfloat16 gYh[BN * HWN * DN];  // attn out hi [b][n][i]
__device__ __align__(128) __nv_bfloat16 gYl[BN * HWN * DN];
__device__ __align__(128) float d_WY[BN * CN * HWN];         // [b][c][n]
__device__ float gPS[CN * 256];
__device__ float gPQ[CN * 256];
__device__ float d_MEAN[CN];
__device__ float d_RSTD[CN];

// ======================= helpers =======================
__device__ __forceinline__ uint32_t smem_u32(const void* p) {
    uint32_t a;
    asm("{ .reg .u64 t; cvta.to.shared.u64 t, %1; cvt.u32.u64 %0, t; }" : "=r"(a) : "l"(p));
    return a;
}
__device__ __forceinline__ void cp16(uint32_t dst, const void* src) {
    asm volatile("cp.async.cg.shared.global [%0], [%1], 16;" :: "r"(dst), "l"(src));
}
#define CP_COMMIT() asm volatile("cp.async.commit_group;" ::: "memory")
#define CP_WAIT0()  asm volatile("cp.async.wait_group 0;" ::: "memory")
#define CP_WAIT1()  asm volatile("cp.async.wait_group 1;" ::: "memory")

__device__ __forceinline__ void mma_bf16(float& c0, float& c1, float& c2, float& c3,
                                         uint32_t a0, uint32_t a1, uint32_t a2, uint32_t a3,
                                         uint32_t b0, uint32_t b1) {
    asm volatile("mma.sync.aligned.m16n8k16.row.col.f32.bf16.bf16.f32 "
                 "{%0,%1,%2,%3}, {%4,%5,%6,%7}, {%8,%9}, {%0,%1,%2,%3};"
                 : "+f"(c0), "+f"(c1), "+f"(c2), "+f"(c3)
                 : "r"(a0), "r"(a1), "r"(a2), "r"(a3), "r"(b0), "r"(b1));
}
__device__ __forceinline__ void mma_f16(float& c0, float& c1, float& c2, float& c3,
                                        uint32_t a0, uint32_t a1, uint32_t a2, uint32_t a3,
                                        uint32_t b0, uint32_t b1) {
    asm volatile("mma.sync.aligned.m16n8k16.row.col.f32.f16.f16.f32 "
                 "{%0,%1,%2,%3}, {%4,%5,%6,%7}, {%8,%9}, {%0,%1,%2,%3};"
                 : "+f"(c0), "+f"(c1), "+f"(c2), "+f"(c3)
                 : "r"(a0), "r"(a1), "r"(a2), "r"(a3), "r"(b0), "r"(b1));
}
__device__ __forceinline__ void mma_f16acc(uint32_t& d0, uint32_t& d1,
                                           uint32_t a0, uint32_t a1, uint32_t a2, uint32_t a3,
                                           uint32_t b0, uint32_t b1) {
    asm volatile("mma.sync.aligned.m16n8k16.row.col.f16.f16.f16.f16 "
                 "{%0,%1}, {%2,%3,%4,%5}, {%6,%7}, {%0,%1};"
                 : "+r"(d0), "+r"(d1)
                 : "r"(a0), "r"(a1), "r"(a2), "r"(a3), "r"(b0), "r"(b1));
}
__device__ __forceinline__ uint32_t lds32(uint32_t addr) {
    uint32_t v;
    asm volatile("ld.shared.b32 %0, [%1];" : "=r"(v) : "r"(addr));
    return v;
}
__device__ __forceinline__ float ex2(float x) {
    float y;
    asm("ex2.approx.ftz.f32 %0, %1;" : "=f"(y) : "f"(x));
    return y;
}
__device__ __forceinline__ void split2(float v0, float v1, uint32_t& hi, uint32_t& lo) {
    __nv_bfloat16 h0 = __float2bfloat16(v0);
    __nv_bfloat16 h1 = __float2bfloat16(v1);
    float r0 = v0 - __bfloat162float(h0);
    float r1 = v1 - __bfloat162float(h1);
    __nv_bfloat162 hh; hh.x = h0; hh.y = h1;
    __nv_bfloat162 ll; ll.x = __float2bfloat16(r0); ll.y = __float2bfloat16(r1);
    hi = *(uint32_t*)&hh;
    lo = *(uint32_t*)&ll;
}
__device__ __forceinline__ uint32_t pack_h2(float v0, float v1) {
    __half2 h = __floats2half2_rn(v0, v1);
    return *(uint32_t*)&h;
}
__device__ __forceinline__ void split1(float v, unsigned short& h, unsigned short& l) {
    __nv_bfloat16 hb = __float2bfloat16(v);
    float r = v - __bfloat162float(hb);
    __nv_bfloat16 lb = __float2bfloat16(r);
    h = *(unsigned short*)&hb;
    l = *(unsigned short*)&lb;
}

// ============================================================================
// K0: pre-split all weights to bf16 hi/lo.
// ============================================================================
__global__ void wsplit_kernel(const float* __restrict__ tw, const float* __restrict__ pw,
                              const float* __restrict__ gw, const float* __restrict__ Ww)
{
    int idx = blockIdx.x * 256 + threadIdx.x;
    if (idx < 49152) {
        int p = idx / 16384, r = idx - p * 16384;
        const float* s = (p == 0) ? tw : (p == 1) ? pw : gw;
        float2 v = *(const float2*)(s + 2 * r);
        uint32_t hi, lo;
        split2(v.x, v.y, hi, lo);
        *(uint32_t*)(gWh + p * 32768 + 2 * r) = hi;
        *(uint32_t*)(gWl + p * 32768 + 2 * r) = lo;
    } else {
        int r = idx - 49152;
        float2 v = *(const float2*)(Ww + 2 * r);
        uint32_t hi, lo;
        split2(v.x, v.y, hi, lo);
        *(uint32_t*)(gWWh + 2 * r) = hi;
        *(uint32_t*)(gWWl + 2 * r) = lo;
    }
}

// ============================================================================
// K0b: transpose+split x -> xT hi/lo [b][n][c].
// ============================================================================
__global__ void xsplit_kernel(const float* __restrict__ x)
{
    __shared__ float xs[64][68];
    const int n0 = blockIdx.x * 64;
    const int c0 = blockIdx.y * 64;
    const int b  = blockIdx.z;
    const int tid = threadIdx.x;
#pragma unroll
    for (int r = 0; r < 4; r++) {
        int fid = tid + (r << 8);
        int cc = fid >> 4, n4 = fid & 15;
        float4 v = *(const float4*)(x + ((size_t)b * CN + c0 + cc) * HWN + n0 + 4 * n4);
        *(float4*)&xs[cc][4 * n4] = v;
    }
    __syncthreads();
#pragma unroll
    for (int r = 0; r < 8; r++) {
        int fid = tid + (r << 8);
        int n = fid >> 5, cp = fid & 31;
        float a  = xs[2 * cp][n];
        float bb = xs[2 * cp + 1][n];
        uint32_t hi, lo;
        split2(a, bb, hi, lo);
        size_t gi = ((size_t)b * HWN + n0 + n) * CN + c0 + 2 * cp;
        *(uint32_t*)(gXh + gi) = hi;
        *(uint32_t*)(gXl + gi) = lo;
    }
}

// ============================================================================
// K1: projections via mma.sync (pre-split operands).
// ============================================================================
__global__ void __launch_bounds__(256) proj_mma_kernel(
    const float* __restrict__ tb, const float* __restrict__ pb, const float* __restrict__ gb)
{
    extern __shared__ char psm[];
    const uint32_t smb = smem_u32(psm);
    unsigned short* sth = (unsigned short*)(psm);            // stage hi [64][130]

    const int p  = blockIdx.x;
    const int n0 = blockIdx.y * 64;
    const int b  = blockIdx.z;
    const float* bias = (p == 0) ? tb : (p == 1) ? pb : gb;

    const int tid  = threadIdx.x;
    const int wrp  = tid >> 5;
    const int lane = tid & 31;
    const int qrow = lane >> 2;
    const int qcol = lane & 3;
    const int i0   = 16 * wrp + qrow;

    float acc[8][4];
#pragma unroll
    for (int i = 0; i < 8; i++)
#pragma unroll
        for (int j = 0; j < 4; j++) acc[i][j] = 0.f;

    for (int c0 = 0; c0 < CN; c0 += 64) {
        __syncthreads();
#pragma unroll
        for (int r = 0; r < 4; r++) {
            int fid = tid + (r << 8);
            int pl = fid >> 9, rem = fid & 511;
            int row = rem >> 3, ch = rem & 7;
            const __nv_bfloat16* src = (pl ? gXl : gXh) +
                ((size_t)b * HWN + n0 + row) * CN + c0 + ch * 8;
            cp16(smb + (pl ? PXL : PXH) + row * 144 + ch * 16, src);
        }
#pragma unroll
        for (int r = 0; r < 8; r++) {
            int fid = tid + (r << 8);
            int pl = fid >> 10, rem = fid & 1023;
            int row = rem >> 3, ch = rem & 7;
            const __nv_bfloat16* src = (pl ? gWl : gWh) +
                (size_t)p * 32768 + row * CN + c0 + ch * 8;
            cp16(smb + (pl ? PWL : PWH) + row * 144 + ch * 16, src);
        }
        CP_COMMIT();
        CP_WAIT0();
        __syncthreads();

        uint32_t ah[4][4], al[4][4];
#pragma unroll
        for (int ks = 0; ks < 4; ks++) {
            uint32_t ko = 32 * ks + 4 * qcol;
            ah[ks][0] = lds32(smb + PWH + i0 * 144 + ko);
            ah[ks][1] = lds32(smb + PWH + (i0 + 8) * 144 + ko);
            ah[ks][2] = lds32(smb + PWH + i0 * 144 + ko + 16);
            ah[ks][3] = lds32(smb + PWH + (i0 + 8) * 144 + ko + 16);
            al[ks][0] = lds32(smb + PWL + i0 * 144 + ko);
            al[ks][1] = lds32(smb + PWL + (i0 + 8) * 144 + ko);
            al[ks][2] = lds32(smb + PWL + i0 * 144 + ko + 16);
            al[ks][3] = lds32(smb + PWL + (i0 + 8) * 144 + ko + 16);
        }
#pragma unroll
        for (int ks = 0; ks < 4; ks++) {
#pragma unroll
            for (int nt = 0; nt < 8; nt++) {
                uint32_t ro = (8 * nt + qrow) * 144 + 32 * ks + 4 * qcol;
                uint32_t bh0 = lds32(smb + PXH + ro);
                uint32_t bh1 = lds32(smb + PXH + ro + 16);
                uint32_t bl0 = lds32(smb + PXL + ro);
                uint32_t bl1 = lds32(smb + PXL + ro + 16);
                mma_bf16(acc[nt][0], acc[nt][1], acc[nt][2], acc[nt][3],
                         ah[ks][0], ah[ks][1], ah[ks][2], ah[ks][3], bh0, bh1);
                mma_bf16(acc[nt][0], acc[nt][1], acc[nt][2], acc[nt][3],
                         ah[ks][0], ah[ks][1], ah[ks][2], ah[ks][3], bl0, bl1);
                mma_bf16(acc[nt][0], acc[nt][1], acc[nt][2], acc[nt][3],
                         al[ks][0], al[ks][1], al[ks][2], al[ks][3], bh0, bh1);
            }
        }
    }

    const float bb0 = bias[i0];
    const float bb1 = bias[i0 + 8];
    const float sc  = (p == 1) ? LOG2E : 1.f;

    if (p < 2) {
        // theta/phi -> single fp16 plane [b][n][k]
        __syncthreads();
#pragma unroll
        for (int nt = 0; nt < 8; nt++) {
            int n = 8 * nt + 2 * qcol;
            float v0 = (acc[nt][0] + bb0) * sc, v1 = (acc[nt][1] + bb0) * sc;
            float v2 = (acc[nt][2] + bb1) * sc, v3 = (acc[nt][3] + bb1) * sc;
            __half h;
            h = __float2half_rn(v0); sth[n * 130 + i0] = *(unsigned short*)&h;
            h = __float2half_rn(v1); sth[(n + 1) * 130 + i0] = *(unsigned short*)&h;
            h = __float2half_rn(v2); sth[n * 130 + i0 + 8] = *(unsigned short*)&h;
            h = __float2half_rn(v3); sth[(n + 1) * 130 + i0 + 8] = *(unsigned short*)&h;
        }
        __syncthreads();
        __half* oh = (p == 0) ? gQh : gKh;
#pragma unroll
        for (int r = 0; r < 16; r++) {
            int t = tid + (r << 8);
            int row = t >> 6, w32 = t & 63;
            uint32_t hv = *(uint32_t*)&sth[row * 130 + 2 * w32];
            size_t gb_ = ((size_t)b * HWN + n0 + row) * DN + 2 * w32;
            *(uint32_t*)(oh + gb_) = hv;
        }
    } else {
        // g -> single fp16 plane [b][d][m]
#pragma unroll
        for (int nt = 0; nt < 8; nt++) {
            int n = n0 + 8 * nt + 2 * qcol;
            float v0 = acc[nt][0] + bb0, v1 = acc[nt][1] + bb0;
            float v2 = acc[nt][2] + bb1, v3 = acc[nt][3] + bb1;
            size_t ba = ((size_t)b * DN + i0) * HWN + n;
            size_t bc = ((size_t)b * DN + i0 + 8) * HWN + n;
            *(uint32_t*)(gVh + ba) = pack_h2(v0, v1);
            *(uint32_t*)(gVh + bc) = pack_h2(v2, v3);
        }
    }
}

// ============================================================================
// K2: flash attention — fp16 single-term S, fp16 P (running max), fp16
//     single-term PV with fp16 accumulators. 128 HMMA per warp-tile.
// ============================================================================
__device__ __forceinline__ void load_kv_tile(uint32_t stg, int b, int m0, int tid) {
#pragma unroll
    for (int r = 0; r < 4; r++) {
        int ch = tid + (r << 8);
        int rw = ch >> 4;
        int kc = ch & 15;
        uint32_t dst = stg + rw * K_ROW + (kc << 4);
        size_t gi = (((size_t)b * HWN + m0 + rw) << 7) + (kc << 3);
        cp16(dst + KH_OFF, gKh + gi);
    }
#pragma unroll
    for (int r = 0; r < 4; r++) {
        int ch = tid + (r << 8);
        int rw = ch >> 3;
        int mc = ch & 7;
        uint32_t dst = stg + rw * V_ROW + (mc << 4);
        size_t gi = (((size_t)b * DN + rw) << 12) + m0 + (mc << 3);
        cp16(dst + VH_OFF, gVh + gi);
    }
}

__global__ void __launch_bounds__(256, 1) attn_mma_kernel()
{
    extern __shared__ char smem[];
    const uint32_t smb = smem_u32(smem);

    const int tid  = threadIdx.x;
    const int lane = tid & 31;
    const int wrp  = tid >> 5;
    const int qrow = lane >> 2;
    const int qcol = lane & 3;
    const int n0   = blockIdx.x * TM;
    const int b    = blockIdx.y;
    const int row0 = 16 * wrp + qrow;

    uint32_t qh[8][4];
    {
        const size_t rbase = ((size_t)b * HWN + n0 + row0) * DN;
#pragma unroll
        for (int ks = 0; ks < 8; ks++) {
            int k0 = 16 * ks + 2 * qcol;
            qh[ks][0] = *(const uint32_t*)(gQh + rbase + k0);
            qh[ks][1] = *(const uint32_t*)(gQh + rbase + 8 * DN + k0);
            qh[ks][2] = *(const uint32_t*)(gQh + rbase + k0 + 8);
            qh[ks][3] = *(const uint32_t*)(gQh + rbase + 8 * DN + k0 + 8);
        }
    }

    float o[16][4];
#pragma unroll
    for (int i = 0; i < 16; i++)
#pragma unroll
        for (int j = 0; j < 4; j++) o[i][j] = 0.f;

    float rs0 = 0.f, rs1 = 0.f;
    float m0 = -INFINITY, m1 = -INFINITY;

    load_kv_tile(smb, b, 0, tid);
    CP_COMMIT();

    for (int t = 0; t < 64; t++) {
        const uint32_t stg = smb + (uint32_t)(t & 1) * STG_SZ;
        __syncthreads();
        if (t + 1 < 64) {
            load_kv_tile(smb + (uint32_t)((t + 1) & 1) * STG_SZ, b, (t + 1) * TN, tid);
            CP_COMMIT();
            CP_WAIT1();
        } else {
            CP_WAIT0();
        }
        __syncthreads();

        // ---- S = q16 K^T (fp16, single term) ----
        float cA[8][4];
#pragma unroll
        for (int nt = 0; nt < 8; nt++) {
            float c0 = 0.f, c1 = 0.f, c2 = 0.f, c3 = 0.f;
            const uint32_t krow = stg + (uint32_t)(8 * nt + qrow) * K_ROW + (uint32_t)(4 * qcol);
#pragma unroll
            for (int ks = 0; ks < 8; ks++) {
                uint32_t bh0 = lds32(krow + KH_OFF + 32 * ks);
                uint32_t bh1 = lds32(krow + KH_OFF + 32 * ks + 16);
                mma_f16(c0, c1, c2, c3, qh[ks][0], qh[ks][1], qh[ks][2], qh[ks][3], bh0, bh1);
            }
            cA[nt][0] = c0; cA[nt][1] = c1; cA[nt][2] = c2; cA[nt][3] = c3;
        }

        // ---- per-tile row max (exp2 domain), running-max rescale ----
        float mx0 = cA[0][0], mx1 = cA[0][2];
#pragma unroll
        for (int nt = 0; nt < 8; nt++) {
            mx0 = fmaxf(mx0, fmaxf(cA[nt][0], cA[nt][1]));
            mx1 = fmaxf(mx1, fmaxf(cA[nt][2], cA[nt][3]));
        }
        mx0 = fmaxf(mx0, __shfl_xor_sync(0xffffffffu, mx0, 1));
        mx0 = fmaxf(mx0, __shfl_xor_sync(0xffffffffu, mx0, 2));
        mx1 = fmaxf(mx1, __shfl_xor_sync(0xffffffffu, mx1, 1));
        mx1 = fmaxf(mx1, __shfl_xor_sync(0xffffffffu, mx1, 2));
        float mn0 = fmaxf(m0, mx0);
        float mn1 = fmaxf(m1, mx1);
        float a0 = ex2(m0 - mn0);
        float a1 = ex2(m1 - mn1);
        m0 = mn0; m1 = mn1;
        rs0 *= a0; rs1 *= a1;
#pragma unroll
        for (int nt = 0; nt < 16; nt++) {
            o[nt][0] *= a0; o[nt][1] *= a0;
            o[nt][2] *= a1; o[nt][3] *= a1;
        }

        // ---- p = 2^(f - m) in fp16 ----
        uint32_t ph[8][2];
#pragma unroll
        for (int nt = 0; nt < 8; nt++) {
            float e0 = ex2(cA[nt][0] - m0), e1 = ex2(cA[nt][1] - m0);
            float e2 = ex2(cA[nt][2] - m1), e3 = ex2(cA[nt][3] - m1);
            rs0 += e0 + e1;
            rs1 += e2 + e3;
            ph[nt][0] = pack_h2(e0, e1);
            ph[nt][1] = pack_h2(e2, e3);
        }

        // ---- O_tile = P V in fp16 accumulators, then add to fp32 O ----
#pragma unroll
        for (int nt = 0; nt < 16; nt++) {
            uint32_t d0 = 0, d1 = 0;
            const uint32_t vrow = stg + VH_OFF + (uint32_t)(8 * nt + qrow) * V_ROW
                                + (uint32_t)(4 * qcol);
#pragma unroll
            for (int ks = 0; ks < 4; ks++) {
                uint32_t bh0 = lds32(vrow + 32 * ks);
                uint32_t bh1 = lds32(vrow + 32 * ks + 16);
                mma_f16acc(d0, d1,
                           ph[2 * ks][0], ph[2 * ks][1],
                           ph[2 * ks + 1][0], ph[2 * ks + 1][1],
                           bh0, bh1);
            }
            float2 f0 = __half22float2(*(__half2*)&d0);
            float2 f1 = __half22float2(*(__half2*)&d1);
            o[nt][0] += f0.x; o[nt][1] += f0.y;
            o[nt][2] += f1.x; o[nt][3] += f1.y;
        }
    }

    rs0 += __shfl_xor_sync(0xffffffffu, rs0, 1);
    rs0 += __shfl_xor_sync(0xffffffffu, rs0, 2);
    rs1 += __shfl_xor_sync(0xffffffffu, rs1, 1);
    rs1 += __shfl_xor_sync(0xffffffffu, rs1, 2);
    float inv0 = 1.f / rs0;
    float inv1 = 1.f / rs1;

    const size_t y0 = ((size_t)b * HWN + n0 + row0) * DN + 2 * qcol;
    const size_t y1 = y0 + 8 * DN;
#pragma unroll
    for (int nt = 0; nt < 16; nt++) {
        uint32_t h0, l0, h1, l1;
        split2(o[nt][0] * inv0, o[nt][1] * inv0, h0, l0);
        split2(o[nt][2] * inv1, o[nt][3] * inv1, h1, l1);
        *(uint32_t*)(gYh + y0 + 8 * nt) = h0;
        *(uint32_t*)(gYl + y0 + 8 * nt) = l0;
        *(uint32_t*)(gYh + y1 + 8 * nt) = h1;
        *(uint32_t*)(gYl + y1 + 8 * nt) = l1;
    }
}

// ============================================================================
// K3: wy = W*y + b via mma.sync, operands pre-split; fused BN partials.
// ============================================================================
__global__ void __launch_bounds__(256) wgemm_mma_kernel(const float* __restrict__ Wb)
{
    extern __shared__ char wsm[];
    const uint32_t smb = smem_u32(wsm);

    const int c0 = blockIdx.x * 128;
    const int n0 = blockIdx.y * 64;
    const int b  = blockIdx.z;
    const int part = blockIdx.y * 4 + blockIdx.z;

    const int tid  = threadIdx.x;
    const int lane = tid & 31;
    const int wrp  = tid >> 5;
    const int qrow = lane >> 2;
    const int qcol = lane & 3;
    const int c    = c0 + 16 * wrp + qrow;

#pragma unroll
    for (int r = 0; r < 8; r++) {
        int fid = tid + (r << 8);
        int pl = fid >> 10, rem = fid & 1023;
        int row = rem >> 4, ch = rem & 15;
        const __nv_bfloat16* src = (pl ? gYl : gYh) +
            ((size_t)b * HWN + n0 + row) * DN + ch * 8;
        cp16(smb + (pl ? WYL : WYH) + row * 272 + ch * 16, src);
    }
    CP_COMMIT();

    uint32_t ah[8][4], al[8][4];
#pragma unroll
    for (int ks = 0; ks < 8; ks++) {
        int k = 16 * ks + 2 * qcol;
        ah[ks][0] = *(const uint32_t*)(gWWh + (size_t)c * DN + k);
        ah[ks][1] = *(const uint32_t*)(gWWh + (size_t)(c + 8) * DN + k);
        ah[ks][2] = *(const uint32_t*)(gWWh + (size_t)c * DN + k + 8);
        ah[ks][3] = *(const uint32_t*)(gWWh + (size_t)(c + 8) * DN + k + 8);
        al[ks][0] = *(const uint32_t*)(gWWl + (size_t)c * DN + k);
        al[ks][1] = *(const uint32_t*)(gWWl + (size_t)(c + 8) * DN + k);
        al[ks][2] = *(const uint32_t*)(gWWl + (size_t)c * DN + k + 8);
        al[ks][3] = *(const uint32_t*)(gWWl + (size_t)(c + 8) * DN + k + 8);
    }
    CP_WAIT0();
    __syncthreads();

    float acc[8][4];
#pragma unroll
    for (int i = 0; i < 8; i++)
#pragma unroll
        for (int j = 0; j < 4; j++) acc[i][j] = 0.f;

#pragma unroll
    for (int ks = 0; ks < 8; ks++) {
#pragma unroll
        for (int nt = 0; nt < 8; nt++) {
            uint32_t ro = (8 * nt + qrow) * 272 + 32 * ks + 4 * qcol;
            uint32_t bh0 = lds32(smb + WYH + ro);
            uint32_t bh1 = lds32(smb + WYH + ro + 16);
            uint32_t bl0 = lds32(smb + WYL + ro);
            uint32_t bl1 = lds32(smb + WYL + ro + 16);
            mma_bf16(acc[nt][0], acc[nt][1], acc[nt][2], acc[nt][3],
                     ah[ks][0], ah[ks][1], ah[ks][2], ah[ks][3], bh0, bh1);
            mma_bf16(acc[nt][0], acc[nt][1], acc[nt][2], acc[nt][3],
                     ah[ks][0], ah[ks][1], ah[ks][2], ah[ks][3], bl0, bl1);
            mma_bf16(acc[nt][0], acc[nt][1], acc[nt][2], acc[nt][3],
                     al[ks][0], al[ks][1], al[ks][2], al[ks][3], bh0, bh1);
        }
    }

    float bb0 = Wb[c], bb1 = Wb[c + 8];
    float s0 = 0.f, q0 = 0.f, s1 = 0.f, q1 = 0.f;
#pragma unroll
    for (int nt = 0; nt < 8; nt++) {
        int n = n0 + 8 * nt + 2 * qcol;
        float v0 = acc[nt][0] + bb0, v1 = acc[nt][1] + bb0;
        float v2 = acc[nt][2] + bb1, v3 = acc[nt][3] + bb1;
        s0 += v0 + v1; q0 += v0 * v0 + v1 * v1;
        s1 += v2 + v3; q1 += v2 * v2 + v3 * v3;
        *(float2*)(d_WY + ((size_t)b * CN + c) * HWN + n)     = make_float2(v0, v1);
        *(float2*)(d_WY + ((size_t)b * CN + c + 8) * HWN + n) = make_float2(v2, v3);
    }
    s0 += __shfl_xor_sync(0xffffffffu, s0, 1);
    s0 += __shfl_xor_sync(0xffffffffu, s0, 2);
    q0 += __shfl_xor_sync(0xffffffffu, q0, 1);
    q0 += __shfl_xor_sync(0xffffffffu, q0, 2);
    s1 += __shfl_xor_sync(0xffffffffu, s1, 1);
    s1 += __shfl_xor_sync(0xffffffffu, s1, 2);
    q1 += __shfl_xor_sync(0xffffffffu, q1, 1);
    q1 += __shfl_xor_sync(0xffffffffu, q1, 2);
    if (qcol == 0) {
        gPS[c * 256 + part] = s0;
        gPQ[c * 256 + part] = q0;
        gPS[(c + 8) * 256 + part] = s1;
        gPQ[(c + 8) * 256 + part] = q1;
    }
}

// ============================================================================
// K4: BN stats finalize
// ============================================================================
__global__ void bnfinal_kernel()
{
    const int c = blockIdx.x;
    const int tid = threadIdx.x;
    __shared__ float sh[256], sh2[256];
    sh[tid]  = gPS[c * 256 + tid];
    sh2[tid] = gPQ[c * 256 + tid];
    __syncthreads();
    for (int off = 128; off > 0; off >>= 1) {
        if (tid < off) { sh[tid] += sh[tid + off]; sh2[tid] += sh2[tid + off]; }
        __syncthreads();
    }
    if (tid == 0) {
        const float invN = 1.f / (float)(BN * HWN);
        float mean = sh[0] * invN;
        float var  = sh2[0] * invN - mean * mean;
        d_MEAN[c] = mean;
        d_RSTD[c] = rsqrtf(var + 1e-5f);
    }
}

// ============================================================================
// K5: finalize
// ============================================================================
__global__ void finalize_kernel(const float* __restrict__ x,
                                const float* __restrict__ gamma,
                                const float* __restrict__ beta,
                                float* __restrict__ out)
{
    int idx = blockIdx.x * blockDim.x + threadIdx.x;
    int c = (idx >> 10) & 255;
    float4 wv = ((const float4*)d_WY)[idx];
    float4 xv = ((const float4*)x)[idx];
    float g  = gamma[c] * d_RSTD[c];
    float m  = d_MEAN[c];
    float bt = beta[c];
    float4 o;
    o.x = (wv.x - m) * g + bt + xv.x;
    o.y = (wv.y - m) * g + bt + xv.y;
    o.z = (wv.z - m) * g + bt + xv.z;
    o.w = (wv.w - m) * g + bt + xv.w;
    ((float4*)out)[idx] = o;
}

// ============================================================================
extern "C" void kernel_launch(void* const* d_in, const int* in_sizes, int n_in,
                              void* d_out, int out_size)
{
    const float* x     = (const float*)d_in[0];
    const float* tw    = (const float*)d_in[1];
    const float* tb    = (const float*)d_in[2];
    const float* pw    = (const float*)d_in[3];
    const float* pb    = (const float*)d_in[4];
    const float* gw    = (const float*)d_in[5];
    const float* gb    = (const float*)d_in[6];
    const float* Ww    = (const float*)d_in[7];
    const float* Wb    = (const float*)d_in[8];
    const float* gamma = (const float*)d_in[9];
    const float* beta  = (const float*)d_in[10];
    float* out = (float*)d_out;

    cudaFuncSetAttribute(proj_mma_kernel, cudaFuncAttributeMaxDynamicSharedMemorySize, PRJ_SMEM);
    cudaFuncSetAttribute(attn_mma_kernel, cudaFuncAttributeMaxDynamicSharedMemorySize, ATTN_SMEM);
    cudaFuncSetAttribute(wgemm_mma_kernel, cudaFuncAttributeMaxDynamicSharedMemorySize, WG_SMEM);

    wsplit_kernel<<<256, 256>>>(tw, pw, gw, Ww);

    dim3 gx(HWN / 64, CN / 64, BN);
    xsplit_kernel<<<gx, 256>>>(x);

    dim3 g1(3, HWN / 64, BN);
    proj_mma_kernel<<<g1, 256, PRJ_SMEM>>>(tb, pb, gb);

    dim3 g2(HWN / TM, BN);
    attn_mma_kernel<<<g2, 256, ATTN_SMEM>>>();

    dim3 g3(2, HWN / 64, BN);
    wgemm_mma_kernel<<<g3, 256, WG_SMEM>>>(Wb);

    bnfinal_kernel<<<CN, 256>>>();

    finalize_kernel<<<(BN * CN * HWN / 4) / 256, 256>>>(x, gamma, beta, out);
}